// round 11
// baseline (speedup 1.0000x reference)
#include <cuda_runtime.h>
#include <math.h>
#include <stdint.h>

#define NN 10000
#define EE 320
#define YW 1920
#define TW 642
#define TWP 644   // padded leading dim for 642-wide buffers (float4 alignment)

// ---------------- device scratch ----------------
__device__ __align__(16) float g_Acat[EE * YW];
__device__ __align__(16) float g_bcat[YW];
__device__ __align__(16) float g_Nq[EE * EE];
__device__ __align__(16) float g_NkIn[EE * EE];
__device__ __align__(16) float g_NkOut[EE * EE];
__device__ __align__(16) float g_NvIn[EE * EE];
__device__ __align__(16) float g_NvOut[EE * EE];
__device__ __align__(16) float g_P[EE * 30];
__device__ __align__(16) float g_MT[EE * TWP];    // [320 x 644(pad)]: M_in | M_out | w_in | w_out
__device__ __align__(16) float g_vc[TW];          // v_in | v_out | const_in | const_out
__device__ __align__(16) float g_G[TW * 30];      // rows: Gin(320) | Gout(320) | gin | gout
__device__ __align__(16) float g_r[30];
__device__ __align__(16) float g_cq[EE];
__device__ __align__(16) float g_ckin[EE];
__device__ __align__(16) float g_ckout[EE];
__device__ __align__(16) float g_cvin[EE];
__device__ __align__(16) float g_cvout[EE];
__device__ __align__(16) float g_Y[(size_t)NN * YW];          // 76.8 MB
__device__ __align__(16) float g_C[(size_t)NN * 32 * EE];     // 409.6 MB
__device__ __align__(16) float g_TQE[(size_t)NN * TWP];       // 25.8 MB

// ---------------- generic 32x32 prep GEMM ----------------
__device__ void gemm32(const float* __restrict__ A, int lda, int tA,
                       const float* __restrict__ B, int ldb, int tB,
                       float* __restrict__ C, int ldc, int M, int Nc)
{
    __shared__ float As[32][33];
    __shared__ float Bs[32][33];
    int bi = blockIdx.x * 32, bj = blockIdx.y * 32;
    if (bi >= M || bj >= Nc) return;
    int tid = threadIdx.x, tx = tid & 15, ty = tid >> 4;
    float a00 = 0.f, a01 = 0.f, a10 = 0.f, a11 = 0.f;
    for (int kt = 0; kt < 320; kt += 32) {
        #pragma unroll
        for (int s = 0; s < 4; s++) {
            int li = tid + s * 256;
            int k = li & 31, r = li >> 5;
            int m = bi + r;
            As[k][r] = (m < M) ? (tA ? A[(size_t)(kt + k) * lda + m]
                                     : A[(size_t)m * lda + kt + k]) : 0.f;
            int nn = bj + r;
            Bs[k][r] = (nn < Nc) ? (tB ? B[(size_t)nn * ldb + kt + k]
                                       : B[(size_t)(kt + k) * ldb + nn]) : 0.f;
        }
        __syncthreads();
        #pragma unroll
        for (int k = 0; k < 32; k++) {
            float x0 = As[k][ty * 2], x1 = As[k][ty * 2 + 1];
            float y0 = Bs[k][tx * 2], y1 = Bs[k][tx * 2 + 1];
            a00 += x0 * y0; a01 += x0 * y1; a10 += x1 * y0; a11 += x1 * y1;
        }
        __syncthreads();
    }
    int r0 = bi + ty * 2, c0 = bj + tx * 2;
    if (r0 < M && c0 < Nc)         C[(size_t)r0 * ldc + c0]           = a00;
    if (r0 < M && c0 + 1 < Nc)     C[(size_t)r0 * ldc + c0 + 1]       = a01;
    if (r0 + 1 < M && c0 < Nc)     C[(size_t)(r0 + 1) * ldc + c0]     = a10;
    if (r0 + 1 < M && c0 + 1 < Nc) C[(size_t)(r0 + 1) * ldc + c0 + 1] = a11;
}

__global__ void __launch_bounds__(256) k1_prep(
    const float* in_Wq, const float* in_Wk, const float* in_Wv, const float* in_qkv_w,
    const float* out_Wq, const float* out_Wk, const float* out_Wv, const float* out_qkv_w,
    const float* in_o_w, const float* out_o_w, const float* fin_qkv_w,
    const float* fin_o_w, const float* Wm)
{
    switch (blockIdx.z) {
    case 0:  gemm32(in_Wq, 320, 0, in_qkv_w,           320, 1, g_Acat + 0,    1920, 320, 320); break;
    case 1:  gemm32(in_Wk, 320, 0, in_qkv_w + 102400,  320, 1, g_Acat + 320,  1920, 320, 320); break;
    case 2:  gemm32(in_Wv, 320, 0, in_qkv_w + 204800,  320, 1, g_Acat + 640,  1920, 320, 320); break;
    case 3:  gemm32(out_Wq, 320, 0, out_qkv_w,          320, 1, g_Acat + 960,  1920, 320, 320); break;
    case 4:  gemm32(out_Wk, 320, 0, out_qkv_w + 102400, 320, 1, g_Acat + 1280, 1920, 320, 320); break;
    case 5:  gemm32(out_Wv, 320, 0, out_qkv_w + 204800, 320, 1, g_Acat + 1600, 1920, 320, 320); break;
    case 6:  gemm32(fin_qkv_w,          320, 0, in_o_w,  320, 0, g_Nq,    320, 320, 320); break;
    case 7:  gemm32(fin_qkv_w + 102400, 320, 0, in_o_w,  320, 0, g_NkIn,  320, 320, 320); break;
    case 8:  gemm32(fin_qkv_w + 102400, 320, 0, out_o_w, 320, 0, g_NkOut, 320, 320, 320); break;
    case 9:  gemm32(fin_qkv_w + 204800, 320, 0, in_o_w,  320, 0, g_NvIn,  320, 320, 320); break;
    case 10: gemm32(fin_qkv_w + 204800, 320, 0, out_o_w, 320, 0, g_NvOut, 320, 320, 320); break;
    case 11: gemm32(fin_o_w, 320, 1, Wm, 30, 0, g_P, 30, 320, 30); break;
    }
}

__global__ void __launch_bounds__(256) k2_prep()
{
    switch (blockIdx.z) {
    case 0: gemm32(g_Nq,    320, 1, g_NkIn,  320, 0, g_MT,        TWP, 320, 320); break;
    case 1: gemm32(g_Nq,    320, 1, g_NkOut, 320, 0, g_MT + 320,  TWP, 320, 320); break;
    case 2: gemm32(g_NvIn,  320, 1, g_P,     30,  0, g_G,         30,  320, 30);  break;
    case 3: gemm32(g_NvOut, 320, 1, g_P,     30,  0, g_G + 9600,  30,  320, 30);  break;
    }
}

// ---------------- prep vectors level A ----------------
__global__ void __launch_bounds__(256) k3a_vec(
    const float* fqw, const float* fqb, const float* in_o_b, const float* out_o_b,
    const float* in_qkv_b, const float* out_qkv_b, const float* fin_o_b, const float* Wm)
{
    int z = blockIdx.x, tid = threadIdx.x;
    if (z == 5) {
        for (int t = tid; t < 1920; t += 256) {
            int cb = t / 320, m = t % 320;
            g_bcat[t] = (cb < 3 ? in_qkv_b : out_qkv_b)[(cb % 3) * 320 + m];
        }
        if (tid < 30) {
            float acc = 0.f;
            for (int j = 0; j < 320; j++) acc += fin_o_b[j] * Wm[j * 30 + tid];
            g_r[tid] = acc;
        }
        return;
    }
    __shared__ float sv[320];
    const float* A; const float* v; const float* b; float* out;
    switch (z) {
    case 0: A = fqw;           v = in_o_b;  b = fqb;       out = g_cq;    break;
    case 1: A = fqw + 102400;  v = in_o_b;  b = fqb + 320; out = g_ckin;  break;
    case 2: A = fqw + 102400;  v = out_o_b; b = fqb + 320; out = g_ckout; break;
    case 3: A = fqw + 204800;  v = in_o_b;  b = fqb + 640; out = g_cvin;  break;
    default:A = fqw + 204800;  v = out_o_b; b = fqb + 640; out = g_cvout; break;
    }
    for (int t = tid; t < 320; t += 256) sv[t] = v[t];
    __syncthreads();
    int w = tid >> 5, lane = tid & 31;
    for (int i = w; i < 320; i += 8) {
        float acc = 0.f;
        for (int j = lane; j < 320; j += 32) acc += A[(size_t)i * 320 + j] * sv[j];
        #pragma unroll
        for (int o = 16; o > 0; o >>= 1) acc += __shfl_down_sync(0xffffffffu, acc, o);
        if (lane == 0) out[i] = acc + b[i];
    }
}

// ---------------- prep vectors level B ----------------
__global__ void __launch_bounds__(320) k3b_vec()
{
    int z = blockIdx.x, tid = threadIdx.x;
    if (z == 6) {
        if (tid < 64) {
            int lane = tid & 31;
            const float* ck = (tid < 32) ? g_ckin : g_ckout;
            float acc = 0.f;
            for (int i = lane; i < 320; i += 32) acc += g_cq[i] * ck[i];
            #pragma unroll
            for (int o = 16; o > 0; o >>= 1) acc += __shfl_down_sync(0xffffffffu, acc, o);
            if (lane == 0) g_vc[640 + (tid >= 32)] = acc;
        }
        return;
    }
    __shared__ float sv[320];
    if (z >= 4) {  // gin / gout rows of G
        const float* cv = (z == 4) ? g_cvin : g_cvout;
        for (int t = tid; t < 320; t += 320) sv[t] = cv[t];
        __syncthreads();
        if (tid < 30) {
            float acc = 0.f;
            for (int i = 0; i < 320; i++) acc += sv[i] * g_P[i * 30 + tid];
            g_G[(z == 4 ? 640 : 641) * 30 + tid] = acc;
        }
        return;
    }
    const float* M; const float* v;
    switch (z) {
    case 0: M = g_NkIn;  v = g_cq;    break;
    case 1: M = g_NkOut; v = g_cq;    break;
    case 2: M = g_Nq;    v = g_ckin;  break;
    default:M = g_Nq;    v = g_ckout; break;
    }
    for (int t = tid; t < 320; t += 320) sv[t] = v[t];
    __syncthreads();
    if (tid < 320) {
        float acc = 0.f;
        for (int i = 0; i < 320; i++) acc += M[(size_t)i * 320 + tid] * sv[i];
        switch (z) {
        case 0: g_vc[tid] = acc; break;
        case 1: g_vc[320 + tid] = acc; break;
        case 2: g_MT[(size_t)tid * TWP + 640] = acc; break;
        default:g_MT[(size_t)tid * TWP + 641] = acc; break;
        }
    }
}

// ---- 128x128-tile double-buffered SGEMM: C = A@B + bias (K=320; ldb,ldc mult of 4) ----
__device__ __forceinline__ void gemm128(const float* __restrict__ A, int lda,
                                        const float* __restrict__ B, int ldb,
                                        const float* __restrict__ bias,
                                        float* __restrict__ C, int ldc, int M, int Nc)
{
    __shared__ __align__(16) float As[2][16 * 132];
    __shared__ __align__(16) float Bs[2][16 * 132];
    const int bi = blockIdx.y * 128, bj = blockIdx.x * 128;
    const int tid = threadIdx.x;
    const int tx = tid & 15, ty = tid >> 4;
    const int ar = tid >> 2, akc = tid & 3;      // A: rows ar, ar+64; k-chunk akc
    const int br = tid >> 4, bc = tid & 15;      // B: row br; col-chunks bc, bc+16
    const int gr0 = bi + ar, gr1 = bi + ar + 64;
    const int gc0 = bj + bc * 4, gc1 = bj + (bc + 16) * 4;

    float acc[8][8] = {};
    float4 sa0, sa1, sb0, sb1;

    // ---- stage loader (gmem -> regs) ----
    auto load_tile = [&](int kt) {
        sa0 = make_float4(0.f, 0.f, 0.f, 0.f);
        sa1 = sa0;
        if (gr0 < M) sa0 = *(const float4*)(A + (size_t)gr0 * lda + kt + akc * 4);
        if (gr1 < M) sa1 = *(const float4*)(A + (size_t)gr1 * lda + kt + akc * 4);
        const float* bp0 = B + (size_t)(kt + br) * ldb + gc0;
        const float* bp1 = B + (size_t)(kt + br) * ldb + gc1;
        if (gc0 + 3 < Nc) sb0 = *(const float4*)bp0;
        else {
            sb0.x = (gc0 + 0 < Nc) ? bp0[0] : 0.f;
            sb0.y = (gc0 + 1 < Nc) ? bp0[1] : 0.f;
            sb0.z = (gc0 + 2 < Nc) ? bp0[2] : 0.f;
            sb0.w = (gc0 + 3 < Nc) ? bp0[3] : 0.f;
        }
        if (gc1 + 3 < Nc) sb1 = *(const float4*)bp1;
        else {
            sb1.x = (gc1 + 0 < Nc) ? bp1[0] : 0.f;
            sb1.y = (gc1 + 1 < Nc) ? bp1[1] : 0.f;
            sb1.z = (gc1 + 2 < Nc) ? bp1[2] : 0.f;
            sb1.w = (gc1 + 3 < Nc) ? bp1[3] : 0.f;
        }
    };
    auto store_tile = [&](int buf) {
        float* as = As[buf];
        as[(akc * 4 + 0) * 132 + ar] = sa0.x;
        as[(akc * 4 + 1) * 132 + ar] = sa0.y;
        as[(akc * 4 + 2) * 132 + ar] = sa0.z;
        as[(akc * 4 + 3) * 132 + ar] = sa0.w;
        as[(akc * 4 + 0) * 132 + ar + 64] = sa1.x;
        as[(akc * 4 + 1) * 132 + ar + 64] = sa1.y;
        as[(akc * 4 + 2) * 132 + ar + 64] = sa1.z;
        as[(akc * 4 + 3) * 132 + ar + 64] = sa1.w;
        *(float4*)&Bs[buf][br * 132 + bc * 4] = sb0;
        *(float4*)&Bs[buf][br * 132 + (bc + 16) * 4] = sb1;
    };

    load_tile(0);
    store_tile(0);
    __syncthreads();

    const int nt = 320 / 16;
    for (int t = 0; t < nt; t++) {
        int cur = t & 1;
        if (t + 1 < nt) load_tile((t + 1) * 16);
        #pragma unroll
        for (int k = 0; k < 16; k++) {
            float af[8], bf[8];
            *(float4*)(af)     = *(const float4*)&As[cur][k * 132 + ty * 8];
            *(float4*)(af + 4) = *(const float4*)&As[cur][k * 132 + ty * 8 + 4];
            *(float4*)(bf)     = *(const float4*)&Bs[cur][k * 132 + tx * 8];
            *(float4*)(bf + 4) = *(const float4*)&Bs[cur][k * 132 + tx * 8 + 4];
            #pragma unroll
            for (int i = 0; i < 8; i++)
                #pragma unroll
                for (int j = 0; j < 8; j++)
                    acc[i][j] += af[i] * bf[j];
        }
        if (t + 1 < nt) {
            store_tile(1 - cur);
            __syncthreads();
        }
    }

    #pragma unroll
    for (int i = 0; i < 8; i++) {
        int r = bi + ty * 8 + i;
        if (r >= M) continue;
        int c0 = bj + tx * 8;
        if (c0 + 7 < Nc) {
            float4 o0, o1;
            o0.x = acc[i][0] + bias[c0];     o0.y = acc[i][1] + bias[c0 + 1];
            o0.z = acc[i][2] + bias[c0 + 2]; o0.w = acc[i][3] + bias[c0 + 3];
            o1.x = acc[i][4] + bias[c0 + 4]; o1.y = acc[i][5] + bias[c0 + 5];
            o1.z = acc[i][6] + bias[c0 + 6]; o1.w = acc[i][7] + bias[c0 + 7];
            *(float4*)(C + (size_t)r * ldc + c0) = o0;
            *(float4*)(C + (size_t)r * ldc + c0 + 4) = o1;
        } else {
            #pragma unroll
            for (int j = 0; j < 8; j++) {
                int c = c0 + j;
                if (c < Nc) C[(size_t)r * ldc + c] = acc[i][j] + bias[c];
            }
        }
    }
}

__global__ void __launch_bounds__(256) k4_proj(const float* __restrict__ X)
{
    gemm128(X, 320, g_Acat, 1920, g_bcat, g_Y, 1920, NN, 1920);
}

__global__ void __launch_bounds__(256) k6_tq()
{
    gemm128(g_C, 10240, g_MT, TWP, g_vc, g_TQE, TWP, NN, TW);
}

// ---------------- per-node 5-head attention (both sides) ----------------
__global__ void __launch_bounds__(256) k5_attn(const int* __restrict__ in_idx,
                                               const int* __restrict__ out_idx)
{
    __shared__ __align__(16) float sA[16 * 324];   // Q, then V
    __shared__ __align__(16) float sB[16 * 324];   // K
    __shared__ float sP[5 * 16 * 16];
    __shared__ int   sIdx[16];
    const int tid = threadIdx.x;
    const int n = blockIdx.x;
    const float4* Y4 = (const float4*)g_Y;

    for (int side = 0; side < 2; side++) {
        __syncthreads();
        if (tid < 16) {
            const int* idx = side ? out_idx : in_idx;
            sIdx[tid] = (tid == 0) ? n : idx[n * 15 + tid - 1];
        }
        __syncthreads();
        {   // gather Q->sA, K->sB
            float4* dA = (float4*)sA;
            float4* dB = (float4*)sB;
            int base = side * 240;
            #pragma unroll
            for (int k = 0; k < 5; k++) {
                int li = tid + k * 256;
                int row = li / 80, f4 = li % 80;
                size_t src = (size_t)sIdx[row] * 480 + base + f4;
                dA[row * 81 + f4] = Y4[src];
                dB[row * 81 + f4] = Y4[src + 80];
            }
        }
        // prefetch V into regs (overlaps L2 latency with score compute)
        float4 vreg[5];
        {
            int base = side * 240 + 160;
            #pragma unroll
            for (int k = 0; k < 5; k++) {
                int li = tid + k * 256;
                int row = li / 80, f4 = li % 80;
                vreg[k] = Y4[(size_t)sIdx[row] * 480 + base + f4];
            }
        }
        __syncthreads();
        {   // scores: 2x2 micro over (l,m), heads split across thread groups
            const float4* Q4 = (const float4*)sA;
            const float4* K4 = (const float4*)sB;
            int l0 = ((tid >> 3) & 7) * 2;
            int m0 = (tid & 7) * 2;
            int h4 = tid >> 6;
            for (int h = h4; h < 5; h += 4) {
                float a00 = 0.f, a01 = 0.f, a10 = 0.f, a11 = 0.f;
                const float4* q0 = Q4 + l0 * 81 + h * 16;
                const float4* q1 = q0 + 81;
                const float4* k0 = K4 + m0 * 81 + h * 16;
                const float4* k1 = k0 + 81;
                #pragma unroll
                for (int i = 0; i < 16; i++) {
                    float4 qa = q0[i], qb = q1[i], ka = k0[i], kb = k1[i];
                    a00 += qa.x * ka.x + qa.y * ka.y + qa.z * ka.z + qa.w * ka.w;
                    a01 += qa.x * kb.x + qa.y * kb.y + qa.z * kb.z + qa.w * kb.w;
                    a10 += qb.x * ka.x + qb.y * ka.y + qb.z * ka.z + qb.w * ka.w;
                    a11 += qb.x * kb.x + qb.y * kb.y + qb.z * kb.z + qb.w * kb.w;
                }
                int b = h * 256 + l0 * 16 + m0;
                sP[b]      = a00 * 0.125f;
                sP[b + 1]  = a01 * 0.125f;
                sP[b + 16] = a10 * 0.125f;
                sP[b + 17] = a11 * 0.125f;
            }
        }
        __syncthreads();
        {   // store prefetched V into sA (Q dead)
            float4* dA = (float4*)sA;
            #pragma unroll
            for (int k = 0; k < 5; k++) {
                int li = tid + k * 256;
                int row = li / 80, f4 = li % 80;
                dA[row * 81 + f4] = vreg[k];
            }
        }
        if (tid < 80) {   // softmax per (h,l)  (touches sP only; runs with V stores)
            float* row = sP + (tid >> 4) * 256 + (tid & 15) * 16;
            float mx = row[0];
            #pragma unroll
            for (int m = 1; m < 16; m++) mx = fmaxf(mx, row[m]);
            float e[16]; float s = 0.f;
            #pragma unroll
            for (int m = 0; m < 16; m++) { e[m] = expf(row[m] - mx); s += e[m]; }
            float inv = 1.f / s;
            #pragma unroll
            for (int m = 0; m < 16; m++) row[m] = e[m] * inv;
        }
        __syncthreads();
        {   // AV -> g_C
            const float4* V4 = (const float4*)sA;
            int l = tid >> 4, c = tid & 15;
            float4* Cout = (float4*)(g_C + ((size_t)n * 32 + side * 16 + l) * 320);
            #pragma unroll
            for (int j = 0; j < 5; j++) {
                float4 acc = make_float4(0.f, 0.f, 0.f, 0.f);
                const float* pr = sP + j * 256 + l * 16;
                const float4* vb = V4 + j * 16 + c;
                #pragma unroll
                for (int m = 0; m < 16; m++) {
                    float w = pr[m];
                    float4 v = vb[m * 81];
                    acc.x += w * v.x; acc.y += w * v.y; acc.z += w * v.z; acc.w += w * v.w;
                }
                Cout[c + 16 * j] = acc;
            }
        }
    }
}

// ---------------- per-node final attention + output projection + ELU ----------------
__global__ void __launch_bounds__(256) k7_final(float* __restrict__ out)
{
    __shared__ __align__(16) float sC[32 * 320];
    __shared__ float sT[644];
    __shared__ float sSc[32];
    __shared__ float sPr[32];
    __shared__ float sAl[2];
    __shared__ float sS[642];
    const int tid = threadIdx.x;
    const int n = blockIdx.x;
    {
        const float4* src = (const float4*)(g_C + (size_t)n * 10240);
        float4* dst = (float4*)sC;
        for (int k = tid; k < 2560; k += 256) dst[k] = src[k];
        const float* tq = g_TQE + (size_t)n * TWP;
        for (int k = tid; k < TW; k += 256) sT[k] = tq[k];
    }
    __syncthreads();
    {   // 32 scores: one warp per 4 tokens
        int w = tid >> 5, lane = tid & 31;
        #pragma unroll
        for (int q = 0; q < 4; q++) {
            int t = w * 4 + q;
            int side = t >> 4;
            const float* tq = sT + side * 320;
            const float* cr = sC + t * 320;
            float acc = 0.f;
            for (int p = lane; p < 320; p += 32) acc += tq[p] * cr[p];
            #pragma unroll
            for (int o = 16; o > 0; o >>= 1) acc += __shfl_down_sync(0xffffffffu, acc, o);
            if (lane == 0) sSc[t] = (acc + sT[640 + side]) * 0.05590169943749474f;
        }
    }
    __syncthreads();
    if (tid < 32) {   // softmax over 32 tokens
        float x = sSc[tid];
        float mx = x;
        #pragma unroll
        for (int o = 16; o > 0; o >>= 1) mx = fmaxf(mx, __shfl_xor_sync(0xffffffffu, mx, o));
        float e = expf(x - mx);
        float s = e;
        #pragma unroll
        for (int o = 16; o > 0; o >>= 1) s += __shfl_xor_sync(0xffffffffu, s, o);
        float ein = (tid < 16) ? e : 0.f;
        #pragma unroll
        for (int o = 16; o > 0; o >>= 1) ein += __shfl_xor_sync(0xffffffffu, ein, o);
        sPr[tid] = e / s;
        if (tid == 0) { sAl[0] = ein / s; sAl[1] = (s - ein) / s; }
    }
    __syncthreads();
    for (int col = tid; col < 640; col += 256) {   // weighted context sums
        int side = col >= 320;
        int p = col - side * 320;
        const float* a = sPr + side * 16;
        const float* c = sC + side * 16 * 320 + p;
        float acc = 0.f;
        #pragma unroll
        for (int t = 0; t < 16; t++) acc += a[t] * c[t * 320];
        sS[col] = acc;
    }
    if (tid == 0) { sS[640] = sAl[0]; sS[641] = sAl[1]; }
    __syncthreads();
    {   // 30 logits, 8 lanes each
        int k = tid >> 3, sub = tid & 7;
        float acc = 0.f;
        if (k < 30)
            for (int p = sub; p < 642; p += 8) acc += sS[p] * g_G[p * 30 + k];
        acc += __shfl_down_sync(0xffffffffu, acc, 4, 8);
        acc += __shfl_down_sync(0xffffffffu, acc, 2, 8);
        acc += __shfl_down_sync(0xffffffffu, acc, 1, 8);
        if (k < 30 && sub == 0) {
            float x = acc + g_r[k];
            out[(size_t)n * 30 + k] = x > 0.f ? x : expm1f(x);
        }
    }
}

extern "C" void kernel_launch(void* const* d_in, const int* in_sizes, int n_in,
                              void* d_out, int out_size)
{
    const float* X         = (const float*)d_in[0];
    const int*   in_idx    = (const int*)d_in[1];
    const int*   out_idx   = (const int*)d_in[2];
    const float* in_Wq     = (const float*)d_in[3];
    const float* in_Wk     = (const float*)d_in[4];
    const float* in_Wv     = (const float*)d_in[5];
    const float* in_qkv_w  = (const float*)d_in[6];
    const float* in_qkv_b  = (const float*)d_in[7];
    const float* in_o_w    = (const float*)d_in[8];
    const float* in_o_b    = (const float*)d_in[9];
    const float* out_Wq    = (const float*)d_in[10];
    const float* out_Wk    = (const float*)d_in[11];
    const float* out_Wv    = (const float*)d_in[12];
    const float* out_qkv_w = (const float*)d_in[13];
    const float* out_qkv_b = (const float*)d_in[14];
    const float* out_o_w   = (const float*)d_in[15];
    const float* out_o_b   = (const float*)d_in[16];
    const float* fin_qkv_w = (const float*)d_in[17];
    const float* fin_qkv_b = (const float*)d_in[18];
    const float* fin_o_w   = (const float*)d_in[19];
    const float* fin_o_b   = (const float*)d_in[20];
    const float* Wm        = (const float*)d_in[21];
    float* out = (float*)d_out;

    k1_prep<<<dim3(10, 10, 12), 256>>>(in_Wq, in_Wk, in_Wv, in_qkv_w,
                                       out_Wq, out_Wk, out_Wv, out_qkv_w,
                                       in_o_w, out_o_w, fin_qkv_w, fin_o_w, Wm);
    k3a_vec<<<6, 256>>>(fin_qkv_w, fin_qkv_b, in_o_b, out_o_b,
                        in_qkv_b, out_qkv_b, fin_o_b, Wm);
    k2_prep<<<dim3(10, 10, 4), 256>>>();
    k3b_vec<<<7, 320>>>();
    k4_proj<<<dim3(15, 79), 256>>>(X);
    k5_attn<<<NN, 256>>>(in_idx, out_idx);
    k6_tq<<<dim3(6, 79), 256>>>();
    k7_final<<<NN, 256>>>(out);
}

// round 12
// speedup vs baseline: 1.4038x; 1.4038x over previous
#include <cuda_runtime.h>
#include <math.h>
#include <stdint.h>

#define NN 10000
#define EE 320
#define YW 1920
#define TW 642
#define TWP 644   // padded leading dim for 642-wide buffers (float4 alignment)

// ---------------- device scratch ----------------
__device__ __align__(16) float g_Acat[EE * YW];
__device__ __align__(16) float g_bcat[YW];
__device__ __align__(16) float g_Nq[EE * EE];
__device__ __align__(16) float g_NkIn[EE * EE];
__device__ __align__(16) float g_NkOut[EE * EE];
__device__ __align__(16) float g_NvIn[EE * EE];
__device__ __align__(16) float g_NvOut[EE * EE];
__device__ __align__(16) float g_P[EE * 30];
__device__ __align__(16) float g_MT[EE * TWP];    // [320 x 644(pad)]: M_in | M_out | w_in | w_out
__device__ __align__(16) float g_vc[TW];          // v_in | v_out | const_in | const_out
__device__ __align__(16) float g_G[TW * 30];      // rows: Gin(320) | Gout(320) | gin | gout
__device__ __align__(16) float g_r[30];
__device__ __align__(16) float g_cq[EE];
__device__ __align__(16) float g_ckin[EE];
__device__ __align__(16) float g_ckout[EE];
__device__ __align__(16) float g_cvin[EE];
__device__ __align__(16) float g_cvout[EE];
__device__ __align__(16) float g_Y[(size_t)NN * YW];          // 76.8 MB
__device__ __align__(16) float g_C[(size_t)NN * 32 * EE];     // 409.6 MB
__device__ __align__(16) float g_TQE[(size_t)NN * TWP];       // 25.8 MB

// ---------------- generic 32x32 prep GEMM ----------------
__device__ void gemm32(const float* __restrict__ A, int lda, int tA,
                       const float* __restrict__ B, int ldb, int tB,
                       float* __restrict__ C, int ldc, int M, int Nc)
{
    __shared__ float As[32][33];
    __shared__ float Bs[32][33];
    int bi = blockIdx.x * 32, bj = blockIdx.y * 32;
    if (bi >= M || bj >= Nc) return;
    int tid = threadIdx.x, tx = tid & 15, ty = tid >> 4;
    float a00 = 0.f, a01 = 0.f, a10 = 0.f, a11 = 0.f;
    for (int kt = 0; kt < 320; kt += 32) {
        #pragma unroll
        for (int s = 0; s < 4; s++) {
            int li = tid + s * 256;
            int k = li & 31, r = li >> 5;
            int m = bi + r;
            As[k][r] = (m < M) ? (tA ? A[(size_t)(kt + k) * lda + m]
                                     : A[(size_t)m * lda + kt + k]) : 0.f;
            int nn = bj + r;
            Bs[k][r] = (nn < Nc) ? (tB ? B[(size_t)nn * ldb + kt + k]
                                       : B[(size_t)(kt + k) * ldb + nn]) : 0.f;
        }
        __syncthreads();
        #pragma unroll
        for (int k = 0; k < 32; k++) {
            float x0 = As[k][ty * 2], x1 = As[k][ty * 2 + 1];
            float y0 = Bs[k][tx * 2], y1 = Bs[k][tx * 2 + 1];
            a00 += x0 * y0; a01 += x0 * y1; a10 += x1 * y0; a11 += x1 * y1;
        }
        __syncthreads();
    }
    int r0 = bi + ty * 2, c0 = bj + tx * 2;
    if (r0 < M && c0 < Nc)         C[(size_t)r0 * ldc + c0]           = a00;
    if (r0 < M && c0 + 1 < Nc)     C[(size_t)r0 * ldc + c0 + 1]       = a01;
    if (r0 + 1 < M && c0 < Nc)     C[(size_t)(r0 + 1) * ldc + c0]     = a10;
    if (r0 + 1 < M && c0 + 1 < Nc) C[(size_t)(r0 + 1) * ldc + c0 + 1] = a11;
}

__global__ void __launch_bounds__(256) k1_prep(
    const float* in_Wq, const float* in_Wk, const float* in_Wv, const float* in_qkv_w,
    const float* out_Wq, const float* out_Wk, const float* out_Wv, const float* out_qkv_w,
    const float* in_o_w, const float* out_o_w, const float* fin_qkv_w,
    const float* fin_o_w, const float* Wm)
{
    switch (blockIdx.z) {
    case 0:  gemm32(in_Wq, 320, 0, in_qkv_w,           320, 1, g_Acat + 0,    1920, 320, 320); break;
    case 1:  gemm32(in_Wk, 320, 0, in_qkv_w + 102400,  320, 1, g_Acat + 320,  1920, 320, 320); break;
    case 2:  gemm32(in_Wv, 320, 0, in_qkv_w + 204800,  320, 1, g_Acat + 640,  1920, 320, 320); break;
    case 3:  gemm32(out_Wq, 320, 0, out_qkv_w,          320, 1, g_Acat + 960,  1920, 320, 320); break;
    case 4:  gemm32(out_Wk, 320, 0, out_qkv_w + 102400, 320, 1, g_Acat + 1280, 1920, 320, 320); break;
    case 5:  gemm32(out_Wv, 320, 0, out_qkv_w + 204800, 320, 1, g_Acat + 1600, 1920, 320, 320); break;
    case 6:  gemm32(fin_qkv_w,          320, 0, in_o_w,  320, 0, g_Nq,    320, 320, 320); break;
    case 7:  gemm32(fin_qkv_w + 102400, 320, 0, in_o_w,  320, 0, g_NkIn,  320, 320, 320); break;
    case 8:  gemm32(fin_qkv_w + 102400, 320, 0, out_o_w, 320, 0, g_NkOut, 320, 320, 320); break;
    case 9:  gemm32(fin_qkv_w + 204800, 320, 0, in_o_w,  320, 0, g_NvIn,  320, 320, 320); break;
    case 10: gemm32(fin_qkv_w + 204800, 320, 0, out_o_w, 320, 0, g_NvOut, 320, 320, 320); break;
    case 11: gemm32(fin_o_w, 320, 1, Wm, 30, 0, g_P, 30, 320, 30); break;
    }
}

__global__ void __launch_bounds__(256) k2_prep()
{
    switch (blockIdx.z) {
    case 0: gemm32(g_Nq,    320, 1, g_NkIn,  320, 0, g_MT,        TWP, 320, 320); break;
    case 1: gemm32(g_Nq,    320, 1, g_NkOut, 320, 0, g_MT + 320,  TWP, 320, 320); break;
    case 2: gemm32(g_NvIn,  320, 1, g_P,     30,  0, g_G,         30,  320, 30);  break;
    case 3: gemm32(g_NvOut, 320, 1, g_P,     30,  0, g_G + 9600,  30,  320, 30);  break;
    }
}

// ---------------- prep vectors level A ----------------
__global__ void __launch_bounds__(256) k3a_vec(
    const float* fqw, const float* fqb, const float* in_o_b, const float* out_o_b,
    const float* in_qkv_b, const float* out_qkv_b, const float* fin_o_b, const float* Wm)
{
    int z = blockIdx.x, tid = threadIdx.x;
    if (z == 5) {
        for (int t = tid; t < 1920; t += 256) {
            int cb = t / 320, m = t % 320;
            g_bcat[t] = (cb < 3 ? in_qkv_b : out_qkv_b)[(cb % 3) * 320 + m];
        }
        if (tid < 30) {
            float acc = 0.f;
            for (int j = 0; j < 320; j++) acc += fin_o_b[j] * Wm[j * 30 + tid];
            g_r[tid] = acc;
        }
        return;
    }
    __shared__ float sv[320];
    const float* A; const float* v; const float* b; float* out;
    switch (z) {
    case 0: A = fqw;           v = in_o_b;  b = fqb;       out = g_cq;    break;
    case 1: A = fqw + 102400;  v = in_o_b;  b = fqb + 320; out = g_ckin;  break;
    case 2: A = fqw + 102400;  v = out_o_b; b = fqb + 320; out = g_ckout; break;
    case 3: A = fqw + 204800;  v = in_o_b;  b = fqb + 640; out = g_cvin;  break;
    default:A = fqw + 204800;  v = out_o_b; b = fqb + 640; out = g_cvout; break;
    }
    for (int t = tid; t < 320; t += 256) sv[t] = v[t];
    __syncthreads();
    int w = tid >> 5, lane = tid & 31;
    for (int i = w; i < 320; i += 8) {
        float acc = 0.f;
        for (int j = lane; j < 320; j += 32) acc += A[(size_t)i * 320 + j] * sv[j];
        #pragma unroll
        for (int o = 16; o > 0; o >>= 1) acc += __shfl_down_sync(0xffffffffu, acc, o);
        if (lane == 0) out[i] = acc + b[i];
    }
}

// ---------------- prep vectors level B ----------------
__global__ void __launch_bounds__(320) k3b_vec()
{
    int z = blockIdx.x, tid = threadIdx.x;
    if (z == 6) {
        if (tid < 64) {
            int lane = tid & 31;
            const float* ck = (tid < 32) ? g_ckin : g_ckout;
            float acc = 0.f;
            for (int i = lane; i < 320; i += 32) acc += g_cq[i] * ck[i];
            #pragma unroll
            for (int o = 16; o > 0; o >>= 1) acc += __shfl_down_sync(0xffffffffu, acc, o);
            if (lane == 0) g_vc[640 + (tid >= 32)] = acc;
        }
        return;
    }
    __shared__ float sv[320];
    if (z >= 4) {  // gin / gout rows of G
        const float* cv = (z == 4) ? g_cvin : g_cvout;
        for (int t = tid; t < 320; t += 320) sv[t] = cv[t];
        __syncthreads();
        if (tid < 30) {
            float acc = 0.f;
            for (int i = 0; i < 320; i++) acc += sv[i] * g_P[i * 30 + tid];
            g_G[(z == 4 ? 640 : 641) * 30 + tid] = acc;
        }
        return;
    }
    const float* M; const float* v;
    switch (z) {
    case 0: M = g_NkIn;  v = g_cq;    break;
    case 1: M = g_NkOut; v = g_cq;    break;
    case 2: M = g_Nq;    v = g_ckin;  break;
    default:M = g_Nq;    v = g_ckout; break;
    }
    for (int t = tid; t < 320; t += 320) sv[t] = v[t];
    __syncthreads();
    if (tid < 320) {
        float acc = 0.f;
        for (int i = 0; i < 320; i++) acc += M[(size_t)i * 320 + tid] * sv[i];
        switch (z) {
        case 0: g_vc[tid] = acc; break;
        case 1: g_vc[320 + tid] = acc; break;
        case 2: g_MT[(size_t)tid * TWP + 640] = acc; break;
        default:g_MT[(size_t)tid * TWP + 641] = acc; break;
        }
    }
}

// ---- 64x64-tile DOUBLE-BUFFERED SGEMM: C = A@B + bias (K=320; ldb,ldc mult of 4) ----
// Identical thread mapping / indexing to the proven single-buffered version;
// only the smem staging is 2-stage (one __syncthreads per k-tile).
__device__ __forceinline__ void gemm64db(const float* __restrict__ A, int lda,
                                         const float* __restrict__ B, int ldb,
                                         const float* __restrict__ bias,
                                         float* __restrict__ C, int ldc, int M, int Nc)
{
    __shared__ __align__(16) float As[2][16 * 68];
    __shared__ __align__(16) float Bs[2][16 * 68];
    const int bi = blockIdx.y * 64, bj = blockIdx.x * 64;
    const int tid = threadIdx.x;
    const int tx = tid & 15, ty = tid >> 4;
    const int arow = tid >> 2, af4 = tid & 3;
    const int brow = tid >> 4, bc4 = tid & 15;
    const int gr = bi + arow;
    const bool aval = gr < M;
    const int gc = bj + bc4 * 4;
    float acc[4][4] = {};
    float4 av, bv;

    // stage 0 load
    {
        av = make_float4(0.f, 0.f, 0.f, 0.f);
        if (aval) av = *(const float4*)(A + (size_t)gr * lda + af4 * 4);
        const float* bp = B + (size_t)brow * ldb + gc;
        if (gc + 3 < Nc) bv = *(const float4*)bp;
        else {
            bv.x = (gc + 0 < Nc) ? bp[0] : 0.f;
            bv.y = (gc + 1 < Nc) ? bp[1] : 0.f;
            bv.z = (gc + 2 < Nc) ? bp[2] : 0.f;
            bv.w = (gc + 3 < Nc) ? bp[3] : 0.f;
        }
        As[0][(af4 * 4 + 0) * 68 + arow] = av.x;
        As[0][(af4 * 4 + 1) * 68 + arow] = av.y;
        As[0][(af4 * 4 + 2) * 68 + arow] = av.z;
        As[0][(af4 * 4 + 3) * 68 + arow] = av.w;
        *(float4*)&Bs[0][brow * 68 + bc4 * 4] = bv;
    }
    __syncthreads();

    const int nt = 320 / 16;
    for (int t = 0; t < nt; t++) {
        const int cur = t & 1;
        if (t + 1 < nt) {
            const int kt = (t + 1) * 16;
            av = make_float4(0.f, 0.f, 0.f, 0.f);
            if (aval) av = *(const float4*)(A + (size_t)gr * lda + kt + af4 * 4);
            const float* bp = B + (size_t)(kt + brow) * ldb + gc;
            if (gc + 3 < Nc) bv = *(const float4*)bp;
            else {
                bv.x = (gc + 0 < Nc) ? bp[0] : 0.f;
                bv.y = (gc + 1 < Nc) ? bp[1] : 0.f;
                bv.z = (gc + 2 < Nc) ? bp[2] : 0.f;
                bv.w = (gc + 3 < Nc) ? bp[3] : 0.f;
            }
        }
        #pragma unroll
        for (int k = 0; k < 16; k++) {
            float4 a = *(const float4*)&As[cur][k * 68 + ty * 4];
            float4 b = *(const float4*)&Bs[cur][k * 68 + tx * 4];
            acc[0][0] += a.x * b.x; acc[0][1] += a.x * b.y; acc[0][2] += a.x * b.z; acc[0][3] += a.x * b.w;
            acc[1][0] += a.y * b.x; acc[1][1] += a.y * b.y; acc[1][2] += a.y * b.z; acc[1][3] += a.y * b.w;
            acc[2][0] += a.z * b.x; acc[2][1] += a.z * b.y; acc[2][2] += a.z * b.z; acc[2][3] += a.z * b.w;
            acc[3][0] += a.w * b.x; acc[3][1] += a.w * b.y; acc[3][2] += a.w * b.z; acc[3][3] += a.w * b.w;
        }
        if (t + 1 < nt) {
            const int nxt = 1 - cur;
            As[nxt][(af4 * 4 + 0) * 68 + arow] = av.x;
            As[nxt][(af4 * 4 + 1) * 68 + arow] = av.y;
            As[nxt][(af4 * 4 + 2) * 68 + arow] = av.z;
            As[nxt][(af4 * 4 + 3) * 68 + arow] = av.w;
            *(float4*)&Bs[nxt][brow * 68 + bc4 * 4] = bv;
            __syncthreads();
        }
    }

    #pragma unroll
    for (int i = 0; i < 4; i++) {
        int r = bi + ty * 4 + i;
        if (r < M) {
            #pragma unroll
            for (int j = 0; j < 4; j++) {
                int c = bj + tx * 4 + j;
                if (c < Nc) C[(size_t)r * ldc + c] = acc[i][j] + bias[c];
            }
        }
    }
}

__global__ void __launch_bounds__(256) k4_proj(const float* __restrict__ X)
{
    gemm64db(X, 320, g_Acat, 1920, g_bcat, g_Y, 1920, NN, 1920);
}

__global__ void __launch_bounds__(256) k6_tq()
{
    gemm64db(g_C, 10240, g_MT, TWP, g_vc, g_TQE, TWP, NN, TW);
}

// ---------------- per-node 5-head attention (both sides) ----------------
__global__ void __launch_bounds__(256) k5_attn(const int* __restrict__ in_idx,
                                               const int* __restrict__ out_idx)
{
    __shared__ __align__(16) float sA[16 * 324];   // Q, then V
    __shared__ __align__(16) float sB[16 * 324];   // K
    __shared__ float sP[5 * 16 * 16];
    __shared__ int   sIdx[16];
    const int tid = threadIdx.x;
    const int n = blockIdx.x;
    const float4* Y4 = (const float4*)g_Y;

    for (int side = 0; side < 2; side++) {
        __syncthreads();
        if (tid < 16) {
            const int* idx = side ? out_idx : in_idx;
            sIdx[tid] = (tid == 0) ? n : idx[n * 15 + tid - 1];
        }
        __syncthreads();
        {   // gather Q->sA, K->sB
            float4* dA = (float4*)sA;
            float4* dB = (float4*)sB;
            int base = side * 240;
            #pragma unroll
            for (int k = 0; k < 5; k++) {
                int li = tid + k * 256;
                int row = li / 80, f4 = li % 80;
                size_t src = (size_t)sIdx[row] * 480 + base + f4;
                dA[row * 81 + f4] = Y4[src];
                dB[row * 81 + f4] = Y4[src + 80];
            }
        }
        __syncthreads();
        {   // scores: 2x2 micro over (l,m), heads split across thread groups
            const float4* Q4 = (const float4*)sA;
            const float4* K4 = (const float4*)sB;
            int l0 = ((tid >> 3) & 7) * 2;
            int m0 = (tid & 7) * 2;
            int h4 = tid >> 6;
            for (int h = h4; h < 5; h += 4) {
                float a00 = 0.f, a01 = 0.f, a10 = 0.f, a11 = 0.f;
                const float4* q0 = Q4 + l0 * 81 + h * 16;
                const float4* q1 = q0 + 81;
                const float4* k0 = K4 + m0 * 81 + h * 16;
                const float4* k1 = k0 + 81;
                #pragma unroll
                for (int i = 0; i < 16; i++) {
                    float4 qa = q0[i], qb = q1[i], ka = k0[i], kb = k1[i];
                    a00 += qa.x * ka.x + qa.y * ka.y + qa.z * ka.z + qa.w * ka.w;
                    a01 += qa.x * kb.x + qa.y * kb.y + qa.z * kb.z + qa.w * kb.w;
                    a10 += qb.x * ka.x + qb.y * ka.y + qb.z * ka.z + qb.w * ka.w;
                    a11 += qb.x * kb.x + qb.y * kb.y + qb.z * kb.z + qb.w * kb.w;
                }
                int b = h * 256 + l0 * 16 + m0;
                sP[b]      = a00 * 0.125f;
                sP[b + 1]  = a01 * 0.125f;
                sP[b + 16] = a10 * 0.125f;
                sP[b + 17] = a11 * 0.125f;
            }
        }
        __syncthreads();
        {   // gather V->sA (Q dead)
            float4* dA = (float4*)sA;
            int base = side * 240 + 160;
            #pragma unroll
            for (int k = 0; k < 5; k++) {
                int li = tid + k * 256;
                int row = li / 80, f4 = li % 80;
                dA[row * 81 + f4] = Y4[(size_t)sIdx[row] * 480 + base + f4];
            }
        }
        if (tid < 80) {   // softmax per (h,l)
            float* row = sP + (tid >> 4) * 256 + (tid & 15) * 16;
            float mx = row[0];
            #pragma unroll
            for (int m = 1; m < 16; m++) mx = fmaxf(mx, row[m]);
            float e[16]; float s = 0.f;
            #pragma unroll
            for (int m = 0; m < 16; m++) { e[m] = expf(row[m] - mx); s += e[m]; }
            float inv = 1.f / s;
            #pragma unroll
            for (int m = 0; m < 16; m++) row[m] = e[m] * inv;
        }
        __syncthreads();
        {   // AV -> g_C
            const float4* V4 = (const float4*)sA;
            int l = tid >> 4, c = tid & 15;
            float4* Cout = (float4*)(g_C + ((size_t)n * 32 + side * 16 + l) * 320);
            #pragma unroll
            for (int j = 0; j < 5; j++) {
                float4 acc = make_float4(0.f, 0.f, 0.f, 0.f);
                const float* pr = sP + j * 256 + l * 16;
                const float4* vb = V4 + j * 16 + c;
                #pragma unroll
                for (int m = 0; m < 16; m++) {
                    float w = pr[m];
                    float4 v = vb[m * 81];
                    acc.x += w * v.x; acc.y += w * v.y; acc.z += w * v.z; acc.w += w * v.w;
                }
                Cout[c + 16 * j] = acc;
            }
        }
    }
}

// ---------------- per-node final attention + output projection + ELU ----------------
__global__ void __launch_bounds__(256) k7_final(float* __restrict__ out)
{
    __shared__ __align__(16) float sC[32 * 320];
    __shared__ float sT[644];
    __shared__ float sSc[32];
    __shared__ float sPr[32];
    __shared__ float sAl[2];
    __shared__ float sS[642];
    const int tid = threadIdx.x;
    const int n = blockIdx.x;
    {
        const float4* src = (const float4*)(g_C + (size_t)n * 10240);
        float4* dst = (float4*)sC;
        for (int k = tid; k < 2560; k += 256) dst[k] = src[k];
        const float* tq = g_TQE + (size_t)n * TWP;
        for (int k = tid; k < TW; k += 256) sT[k] = tq[k];
    }
    __syncthreads();
    {   // 32 scores: one warp per 4 tokens
        int w = tid >> 5, lane = tid & 31;
        #pragma unroll
        for (int q = 0; q < 4; q++) {
            int t = w * 4 + q;
            int side = t >> 4;
            const float* tq = sT + side * 320;
            const float* cr = sC + t * 320;
            float acc = 0.f;
            for (int p = lane; p < 320; p += 32) acc += tq[p] * cr[p];
            #pragma unroll
            for (int o = 16; o > 0; o >>= 1) acc += __shfl_down_sync(0xffffffffu, acc, o);
            if (lane == 0) sSc[t] = (acc + sT[640 + side]) * 0.05590169943749474f;
        }
    }
    __syncthreads();
    if (tid < 32) {   // softmax over 32 tokens
        float x = sSc[tid];
        float mx = x;
        #pragma unroll
        for (int o = 16; o > 0; o >>= 1) mx = fmaxf(mx, __shfl_xor_sync(0xffffffffu, mx, o));
        float e = expf(x - mx);
        float s = e;
        #pragma unroll
        for (int o = 16; o > 0; o >>= 1) s += __shfl_xor_sync(0xffffffffu, s, o);
        float ein = (tid < 16) ? e : 0.f;
        #pragma unroll
        for (int o = 16; o > 0; o >>= 1) ein += __shfl_xor_sync(0xffffffffu, ein, o);
        sPr[tid] = e / s;
        if (tid == 0) { sAl[0] = ein / s; sAl[1] = (s - ein) / s; }
    }
    __syncthreads();
    for (int col = tid; col < 640; col += 256) {   // weighted context sums
        int side = col >= 320;
        int p = col - side * 320;
        const float* a = sPr + side * 16;
        const float* c = sC + side * 16 * 320 + p;
        float acc = 0.f;
        #pragma unroll
        for (int t = 0; t < 16; t++) acc += a[t] * c[t * 320];
        sS[col] = acc;
    }
    if (tid == 0) { sS[640] = sAl[0]; sS[641] = sAl[1]; }
    __syncthreads();
    {   // 30 logits, 8 lanes each
        int k = tid >> 3, sub = tid & 7;
        float acc = 0.f;
        if (k < 30)
            for (int p = sub; p < 642; p += 8) acc += sS[p] * g_G[p * 30 + k];
        acc += __shfl_down_sync(0xffffffffu, acc, 4, 8);
        acc += __shfl_down_sync(0xffffffffu, acc, 2, 8);
        acc += __shfl_down_sync(0xffffffffu, acc, 1, 8);
        if (k < 30 && sub == 0) {
            float x = acc + g_r[k];
            out[(size_t)n * 30 + k] = x > 0.f ? x : expm1f(x);
        }
    }
}

extern "C" void kernel_launch(void* const* d_in, const int* in_sizes, int n_in,
                              void* d_out, int out_size)
{
    const float* X         = (const float*)d_in[0];
    const int*   in_idx    = (const int*)d_in[1];
    const int*   out_idx   = (const int*)d_in[2];
    const float* in_Wq     = (const float*)d_in[3];
    const float* in_Wk     = (const float*)d_in[4];
    const float* in_Wv     = (const float*)d_in[5];
    const float* in_qkv_w  = (const float*)d_in[6];
    const float* in_qkv_b  = (const float*)d_in[7];
    const float* in_o_w    = (const float*)d_in[8];
    const float* in_o_b    = (const float*)d_in[9];
    const float* out_Wq    = (const float*)d_in[10];
    const float* out_Wk    = (const float*)d_in[11];
    const float* out_Wv    = (const float*)d_in[12];
    const float* out_qkv_w = (const float*)d_in[13];
    const float* out_qkv_b = (const float*)d_in[14];
    const float* out_o_w   = (const float*)d_in[15];
    const float* out_o_b   = (const float*)d_in[16];
    const float* fin_qkv_w = (const float*)d_in[17];
    const float* fin_qkv_b = (const float*)d_in[18];
    const float* fin_o_w   = (const float*)d_in[19];
    const float* fin_o_b   = (const float*)d_in[20];
    const float* Wm        = (const float*)d_in[21];
    float* out = (float*)d_out;

    // NOTE: k4 moved before k3b (legal: k4 needs only k1+k3a) so the ncu
    // capture slot (4th app launch) profiles k4_proj instead of k3b_vec.
    k1_prep<<<dim3(10, 10, 12), 256>>>(in_Wq, in_Wk, in_Wv, in_qkv_w,
                                       out_Wq, out_Wk, out_Wv, out_qkv_w,
                                       in_o_w, out_o_w, fin_qkv_w, fin_o_w, Wm);
    k3a_vec<<<6, 256>>>(fin_qkv_w, fin_qkv_b, in_o_b, out_o_b,
                        in_qkv_b, out_qkv_b, fin_o_b, Wm);
    k2_prep<<<dim3(10, 10, 4), 256>>>();
    k4_proj<<<dim3(30, 157), 256>>>(X);
    k3b_vec<<<7, 320>>>();
    k5_attn<<<NN, 256>>>(in_idx, out_idx);
    k6_tq<<<dim3(11, 157), 256>>>();
    k7_final<<<NN, 256>>>(out);
}

// round 13
// speedup vs baseline: 1.5580x; 1.1098x over previous
#include <cuda_runtime.h>
#include <math.h>
#include <stdint.h>

#define NN 10000
#define EE 320
#define YW 1920
#define TW 642
#define TWP 644   // padded leading dim for 642-wide buffers (float4 alignment)

// ---------------- device scratch ----------------
__device__ __align__(16) float g_Acat[EE * YW];
__device__ __align__(16) float g_bcat[YW];
__device__ __align__(16) float g_Nq[EE * EE];
__device__ __align__(16) float g_NkIn[EE * EE];
__device__ __align__(16) float g_NkOut[EE * EE];
__device__ __align__(16) float g_NvIn[EE * EE];
__device__ __align__(16) float g_NvOut[EE * EE];
__device__ __align__(16) float g_P[EE * 30];
__device__ __align__(16) float g_MT[EE * TWP];    // [320 x 644(pad)]: M_in | M_out | w_in | w_out
__device__ __align__(16) float g_vc[TW];          // v_in | v_out | const_in | const_out
__device__ __align__(16) float g_G[TW * 30];      // rows: Gin(320) | Gout(320) | gin | gout
__device__ __align__(16) float g_r[30];
__device__ __align__(16) float g_cq[EE];
__device__ __align__(16) float g_ckin[EE];
__device__ __align__(16) float g_ckout[EE];
__device__ __align__(16) float g_cvin[EE];
__device__ __align__(16) float g_cvout[EE];
__device__ __align__(16) float g_Y[(size_t)NN * YW];          // 76.8 MB
__device__ __align__(16) float g_C[(size_t)NN * 32 * EE];     // 409.6 MB
__device__ __align__(16) float g_TQE[(size_t)NN * TWP];       // 25.8 MB

// ---------------- generic 32x32 prep GEMM ----------------
__device__ void gemm32(const float* __restrict__ A, int lda, int tA,
                       const float* __restrict__ B, int ldb, int tB,
                       float* __restrict__ C, int ldc, int M, int Nc)
{
    __shared__ float As[32][33];
    __shared__ float Bs[32][33];
    int bi = blockIdx.x * 32, bj = blockIdx.y * 32;
    if (bi >= M || bj >= Nc) return;
    int tid = threadIdx.x, tx = tid & 15, ty = tid >> 4;
    float a00 = 0.f, a01 = 0.f, a10 = 0.f, a11 = 0.f;
    for (int kt = 0; kt < 320; kt += 32) {
        #pragma unroll
        for (int s = 0; s < 4; s++) {
            int li = tid + s * 256;
            int k = li & 31, r = li >> 5;
            int m = bi + r;
            As[k][r] = (m < M) ? (tA ? A[(size_t)(kt + k) * lda + m]
                                     : A[(size_t)m * lda + kt + k]) : 0.f;
            int nn = bj + r;
            Bs[k][r] = (nn < Nc) ? (tB ? B[(size_t)nn * ldb + kt + k]
                                       : B[(size_t)(kt + k) * ldb + nn]) : 0.f;
        }
        __syncthreads();
        #pragma unroll
        for (int k = 0; k < 32; k++) {
            float x0 = As[k][ty * 2], x1 = As[k][ty * 2 + 1];
            float y0 = Bs[k][tx * 2], y1 = Bs[k][tx * 2 + 1];
            a00 += x0 * y0; a01 += x0 * y1; a10 += x1 * y0; a11 += x1 * y1;
        }
        __syncthreads();
    }
    int r0 = bi + ty * 2, c0 = bj + tx * 2;
    if (r0 < M && c0 < Nc)         C[(size_t)r0 * ldc + c0]           = a00;
    if (r0 < M && c0 + 1 < Nc)     C[(size_t)r0 * ldc + c0 + 1]       = a01;
    if (r0 + 1 < M && c0 < Nc)     C[(size_t)(r0 + 1) * ldc + c0]     = a10;
    if (r0 + 1 < M && c0 + 1 < Nc) C[(size_t)(r0 + 1) * ldc + c0 + 1] = a11;
}

__global__ void __launch_bounds__(256) k1_prep(
    const float* in_Wq, const float* in_Wk, const float* in_Wv, const float* in_qkv_w,
    const float* out_Wq, const float* out_Wk, const float* out_Wv, const float* out_qkv_w,
    const float* in_o_w, const float* out_o_w, const float* fin_qkv_w,
    const float* fin_o_w, const float* Wm)
{
    switch (blockIdx.z) {
    case 0:  gemm32(in_Wq, 320, 0, in_qkv_w,           320, 1, g_Acat + 0,    1920, 320, 320); break;
    case 1:  gemm32(in_Wk, 320, 0, in_qkv_w + 102400,  320, 1, g_Acat + 320,  1920, 320, 320); break;
    case 2:  gemm32(in_Wv, 320, 0, in_qkv_w + 204800,  320, 1, g_Acat + 640,  1920, 320, 320); break;
    case 3:  gemm32(out_Wq, 320, 0, out_qkv_w,          320, 1, g_Acat + 960,  1920, 320, 320); break;
    case 4:  gemm32(out_Wk, 320, 0, out_qkv_w + 102400, 320, 1, g_Acat + 1280, 1920, 320, 320); break;
    case 5:  gemm32(out_Wv, 320, 0, out_qkv_w + 204800, 320, 1, g_Acat + 1600, 1920, 320, 320); break;
    case 6:  gemm32(fin_qkv_w,          320, 0, in_o_w,  320, 0, g_Nq,    320, 320, 320); break;
    case 7:  gemm32(fin_qkv_w + 102400, 320, 0, in_o_w,  320, 0, g_NkIn,  320, 320, 320); break;
    case 8:  gemm32(fin_qkv_w + 102400, 320, 0, out_o_w, 320, 0, g_NkOut, 320, 320, 320); break;
    case 9:  gemm32(fin_qkv_w + 204800, 320, 0, in_o_w,  320, 0, g_NvIn,  320, 320, 320); break;
    case 10: gemm32(fin_qkv_w + 204800, 320, 0, out_o_w, 320, 0, g_NvOut, 320, 320, 320); break;
    case 11: gemm32(fin_o_w, 320, 1, Wm, 30, 0, g_P, 30, 320, 30); break;
    }
}

__global__ void __launch_bounds__(256) k2_prep()
{
    switch (blockIdx.z) {
    case 0: gemm32(g_Nq,    320, 1, g_NkIn,  320, 0, g_MT,        TWP, 320, 320); break;
    case 1: gemm32(g_Nq,    320, 1, g_NkOut, 320, 0, g_MT + 320,  TWP, 320, 320); break;
    case 2: gemm32(g_NvIn,  320, 1, g_P,     30,  0, g_G,         30,  320, 30);  break;
    case 3: gemm32(g_NvOut, 320, 1, g_P,     30,  0, g_G + 9600,  30,  320, 30);  break;
    }
}

// ---------------- prep vectors level A ----------------
__global__ void __launch_bounds__(256) k3a_vec(
    const float* fqw, const float* fqb, const float* in_o_b, const float* out_o_b,
    const float* in_qkv_b, const float* out_qkv_b, const float* fin_o_b, const float* Wm)
{
    int z = blockIdx.x, tid = threadIdx.x;
    if (z == 5) {
        for (int t = tid; t < 1920; t += 256) {
            int cb = t / 320, m = t % 320;
            g_bcat[t] = (cb < 3 ? in_qkv_b : out_qkv_b)[(cb % 3) * 320 + m];
        }
        if (tid < 30) {
            float acc = 0.f;
            for (int j = 0; j < 320; j++) acc += fin_o_b[j] * Wm[j * 30 + tid];
            g_r[tid] = acc;
        }
        return;
    }
    __shared__ float sv[320];
    const float* A; const float* v; const float* b; float* out;
    switch (z) {
    case 0: A = fqw;           v = in_o_b;  b = fqb;       out = g_cq;    break;
    case 1: A = fqw + 102400;  v = in_o_b;  b = fqb + 320; out = g_ckin;  break;
    case 2: A = fqw + 102400;  v = out_o_b; b = fqb + 320; out = g_ckout; break;
    case 3: A = fqw + 204800;  v = in_o_b;  b = fqb + 640; out = g_cvin;  break;
    default:A = fqw + 204800;  v = out_o_b; b = fqb + 640; out = g_cvout; break;
    }
    for (int t = tid; t < 320; t += 256) sv[t] = v[t];
    __syncthreads();
    int w = tid >> 5, lane = tid & 31;
    for (int i = w; i < 320; i += 8) {
        float acc = 0.f;
        for (int j = lane; j < 320; j += 32) acc += A[(size_t)i * 320 + j] * sv[j];
        #pragma unroll
        for (int o = 16; o > 0; o >>= 1) acc += __shfl_down_sync(0xffffffffu, acc, o);
        if (lane == 0) out[i] = acc + b[i];
    }
}

// ---------------- prep vectors level B ----------------
__global__ void __launch_bounds__(320) k3b_vec()
{
    int z = blockIdx.x, tid = threadIdx.x;
    if (z == 6) {
        if (tid < 64) {
            int lane = tid & 31;
            const float* ck = (tid < 32) ? g_ckin : g_ckout;
            float acc = 0.f;
            for (int i = lane; i < 320; i += 32) acc += g_cq[i] * ck[i];
            #pragma unroll
            for (int o = 16; o > 0; o >>= 1) acc += __shfl_down_sync(0xffffffffu, acc, o);
            if (lane == 0) g_vc[640 + (tid >= 32)] = acc;
        }
        return;
    }
    __shared__ float sv[320];
    if (z >= 4) {  // gin / gout rows of G
        const float* cv = (z == 4) ? g_cvin : g_cvout;
        for (int t = tid; t < 320; t += 320) sv[t] = cv[t];
        __syncthreads();
        if (tid < 30) {
            float acc = 0.f;
            for (int i = 0; i < 320; i++) acc += sv[i] * g_P[i * 30 + tid];
            g_G[(z == 4 ? 640 : 641) * 30 + tid] = acc;
        }
        return;
    }
    const float* M; const float* v;
    switch (z) {
    case 0: M = g_NkIn;  v = g_cq;    break;
    case 1: M = g_NkOut; v = g_cq;    break;
    case 2: M = g_Nq;    v = g_ckin;  break;
    default:M = g_Nq;    v = g_ckout; break;
    }
    for (int t = tid; t < 320; t += 320) sv[t] = v[t];
    __syncthreads();
    if (tid < 320) {
        float acc = 0.f;
        for (int i = 0; i < 320; i++) acc += M[(size_t)i * 320 + tid] * sv[i];
        switch (z) {
        case 0: g_vc[tid] = acc; break;
        case 1: g_vc[320 + tid] = acc; break;
        case 2: g_MT[(size_t)tid * TWP + 640] = acc; break;
        default:g_MT[(size_t)tid * TWP + 641] = acc; break;
        }
    }
}

// ---- 128x64-tile double-buffered SGEMM, 8x4 micro: C = A@B + bias ----
// 3 LDS.128 per 32 FMA per thread (1.5 B/FMA) -> below crossbar roofline.
// K fixed at 320; ldb, ldc must be multiples of 4.
__device__ __forceinline__ void gemm128x64(const float* __restrict__ A, int lda,
                                           const float* __restrict__ B, int ldb,
                                           const float* __restrict__ bias,
                                           float* __restrict__ C, int ldc, int M, int Nc)
{
    __shared__ __align__(16) float As[2][16 * 132];   // [k][row], 128 rows + pad
    __shared__ __align__(16) float Bs[2][16 * 68];    // [k][col], 64 cols + pad
    const int bi = blockIdx.y * 128, bj = blockIdx.x * 64;
    const int tid = threadIdx.x;
    const int tx = tid & 15, ty = tid >> 4;          // micro: rows ty*8.., cols tx*4..
    const int ar = tid >> 2, akc = tid & 3;          // A loader: rows ar, ar+64
    const int brow = tid >> 4, bc4 = tid & 15;       // B loader
    const int gr0 = bi + ar, gr1 = bi + ar + 64;
    const bool av0 = gr0 < M, av1 = gr1 < M;
    const int gc = bj + bc4 * 4;
    float acc[8][4] = {};
    float4 sa0, sa1, sb;

    auto load_g = [&](int kt) {
        sa0 = make_float4(0.f, 0.f, 0.f, 0.f);
        sa1 = sa0;
        if (av0) sa0 = *(const float4*)(A + (size_t)gr0 * lda + kt + akc * 4);
        if (av1) sa1 = *(const float4*)(A + (size_t)gr1 * lda + kt + akc * 4);
        const float* bp = B + (size_t)(kt + brow) * ldb + gc;
        if (gc + 3 < Nc) sb = *(const float4*)bp;
        else {
            sb.x = (gc + 0 < Nc) ? bp[0] : 0.f;
            sb.y = (gc + 1 < Nc) ? bp[1] : 0.f;
            sb.z = (gc + 2 < Nc) ? bp[2] : 0.f;
            sb.w = (gc + 3 < Nc) ? bp[3] : 0.f;
        }
    };
    auto store_s = [&](int buf) {
        float* as = As[buf];
        as[(akc * 4 + 0) * 132 + ar] = sa0.x;
        as[(akc * 4 + 1) * 132 + ar] = sa0.y;
        as[(akc * 4 + 2) * 132 + ar] = sa0.z;
        as[(akc * 4 + 3) * 132 + ar] = sa0.w;
        as[(akc * 4 + 0) * 132 + ar + 64] = sa1.x;
        as[(akc * 4 + 1) * 132 + ar + 64] = sa1.y;
        as[(akc * 4 + 2) * 132 + ar + 64] = sa1.z;
        as[(akc * 4 + 3) * 132 + ar + 64] = sa1.w;
        *(float4*)&Bs[buf][brow * 68 + bc4 * 4] = sb;
    };

    load_g(0);
    store_s(0);
    __syncthreads();

    const int nt = 320 / 16;
    for (int t = 0; t < nt; t++) {
        const int cur = t & 1;
        if (t + 1 < nt) load_g((t + 1) * 16);
        #pragma unroll
        for (int k = 0; k < 16; k++) {
            float af[8], bf[4];
            *(float4*)(af)     = *(const float4*)&As[cur][k * 132 + ty * 8];
            *(float4*)(af + 4) = *(const float4*)&As[cur][k * 132 + ty * 8 + 4];
            *(float4*)(bf)     = *(const float4*)&Bs[cur][k * 68 + tx * 4];
            #pragma unroll
            for (int i = 0; i < 8; i++)
                #pragma unroll
                for (int j = 0; j < 4; j++)
                    acc[i][j] += af[i] * bf[j];
        }
        if (t + 1 < nt) {
            store_s(1 - cur);
            __syncthreads();
        }
    }

    #pragma unroll
    for (int i = 0; i < 8; i++) {
        int r = bi + ty * 8 + i;
        if (r >= M) continue;
        int c0 = bj + tx * 4;
        if (c0 + 3 < Nc) {
            float4 o;
            o.x = acc[i][0] + bias[c0];
            o.y = acc[i][1] + bias[c0 + 1];
            o.z = acc[i][2] + bias[c0 + 2];
            o.w = acc[i][3] + bias[c0 + 3];
            *(float4*)(C + (size_t)r * ldc + c0) = o;
        } else {
            #pragma unroll
            for (int j = 0; j < 4; j++) {
                int c = c0 + j;
                if (c < Nc) C[(size_t)r * ldc + c] = acc[i][j] + bias[c];
            }
        }
    }
}

__global__ void __launch_bounds__(256) k4_proj(const float* __restrict__ X)
{
    gemm128x64(X, 320, g_Acat, 1920, g_bcat, g_Y, 1920, NN, 1920);
}

__global__ void __launch_bounds__(256) k6_tq()
{
    gemm128x64(g_C, 10240, g_MT, TWP, g_vc, g_TQE, TWP, NN, TW);
}

// ---------------- per-node 5-head attention (both sides) ----------------
__global__ void __launch_bounds__(256) k5_attn(const int* __restrict__ in_idx,
                                               const int* __restrict__ out_idx)
{
    __shared__ __align__(16) float sA[16 * 324];   // Q, then V
    __shared__ __align__(16) float sB[16 * 324];   // K
    __shared__ float sP[5 * 16 * 16];
    __shared__ int   sIdx[16];
    const int tid = threadIdx.x;
    const int n = blockIdx.x;
    const float4* Y4 = (const float4*)g_Y;

    for (int side = 0; side < 2; side++) {
        __syncthreads();
        if (tid < 16) {
            const int* idx = side ? out_idx : in_idx;
            sIdx[tid] = (tid == 0) ? n : idx[n * 15 + tid - 1];
        }
        __syncthreads();
        {   // gather Q->sA, K->sB
            float4* dA = (float4*)sA;
            float4* dB = (float4*)sB;
            int base = side * 240;
            #pragma unroll
            for (int k = 0; k < 5; k++) {
                int li = tid + k * 256;
                int row = li / 80, f4 = li % 80;
                size_t src = (size_t)sIdx[row] * 480 + base + f4;
                dA[row * 81 + f4] = Y4[src];
                dB[row * 81 + f4] = Y4[src + 80];
            }
        }
        __syncthreads();
        {   // scores: 2x2 micro over (l,m), heads split across thread groups
            const float4* Q4 = (const float4*)sA;
            const float4* K4 = (const float4*)sB;
            int l0 = ((tid >> 3) & 7) * 2;
            int m0 = (tid & 7) * 2;
            int h4 = tid >> 6;
            for (int h = h4; h < 5; h += 4) {
                float a00 = 0.f, a01 = 0.f, a10 = 0.f, a11 = 0.f;
                const float4* q0 = Q4 + l0 * 81 + h * 16;
                const float4* q1 = q0 + 81;
                const float4* k0 = K4 + m0 * 81 + h * 16;
                const float4* k1 = k0 + 81;
                #pragma unroll
                for (int i = 0; i < 16; i++) {
                    float4 qa = q0[i], qb = q1[i], ka = k0[i], kb = k1[i];
                    a00 += qa.x * ka.x + qa.y * ka.y + qa.z * ka.z + qa.w * ka.w;
                    a01 += qa.x * kb.x + qa.y * kb.y + qa.z * kb.z + qa.w * kb.w;
                    a10 += qb.x * ka.x + qb.y * ka.y + qb.z * ka.z + qb.w * ka.w;
                    a11 += qb.x * kb.x + qb.y * kb.y + qb.z * kb.z + qb.w * kb.w;
                }
                int b = h * 256 + l0 * 16 + m0;
                sP[b]      = a00 * 0.125f;
                sP[b + 1]  = a01 * 0.125f;
                sP[b + 16] = a10 * 0.125f;
                sP[b + 17] = a11 * 0.125f;
            }
        }
        __syncthreads();
        {   // gather V->sA (Q dead)
            float4* dA = (float4*)sA;
            int base = side * 240 + 160;
            #pragma unroll
            for (int k = 0; k < 5; k++) {
                int li = tid + k * 256;
                int row = li / 80, f4 = li % 80;
                dA[row * 81 + f4] = Y4[(size_t)sIdx[row] * 480 + base + f4];
            }
        }
        if (tid < 80) {   // softmax per (h,l)
            float* row = sP + (tid >> 4) * 256 + (tid & 15) * 16;
            float mx = row[0];
            #pragma unroll
            for (int m = 1; m < 16; m++) mx = fmaxf(mx, row[m]);
            float e[16]; float s = 0.f;
            #pragma unroll
            for (int m = 0; m < 16; m++) { e[m] = expf(row[m] - mx); s += e[m]; }
            float inv = 1.f / s;
            #pragma unroll
            for (int m = 0; m < 16; m++) row[m] = e[m] * inv;
        }
        __syncthreads();
        {   // AV -> g_C
            const float4* V4 = (const float4*)sA;
            int l = tid >> 4, c = tid & 15;
            float4* Cout = (float4*)(g_C + ((size_t)n * 32 + side * 16 + l) * 320);
            #pragma unroll
            for (int j = 0; j < 5; j++) {
                float4 acc = make_float4(0.f, 0.f, 0.f, 0.f);
                const float* pr = sP + j * 256 + l * 16;
                const float4* vb = V4 + j * 16 + c;
                #pragma unroll
                for (int m = 0; m < 16; m++) {
                    float w = pr[m];
                    float4 v = vb[m * 81];
                    acc.x += w * v.x; acc.y += w * v.y; acc.z += w * v.z; acc.w += w * v.w;
                }
                Cout[c + 16 * j] = acc;
            }
        }
    }
}

// ---------------- per-node final attention + output projection + ELU ----------------
__global__ void __launch_bounds__(256) k7_final(float* __restrict__ out)
{
    __shared__ __align__(16) float sC[32 * 320];
    __shared__ float sT[644];
    __shared__ float sSc[32];
    __shared__ float sPr[32];
    __shared__ float sAl[2];
    __shared__ float sS[642];
    const int tid = threadIdx.x;
    const int n = blockIdx.x;
    {
        const float4* src = (const float4*)(g_C + (size_t)n * 10240);
        float4* dst = (float4*)sC;
        for (int k = tid; k < 2560; k += 256) dst[k] = src[k];
        const float* tq = g_TQE + (size_t)n * TWP;
        for (int k = tid; k < TW; k += 256) sT[k] = tq[k];
    }
    __syncthreads();
    {   // 32 scores: one warp per 4 tokens
        int w = tid >> 5, lane = tid & 31;
        #pragma unroll
        for (int q = 0; q < 4; q++) {
            int t = w * 4 + q;
            int side = t >> 4;
            const float* tq = sT + side * 320;
            const float* cr = sC + t * 320;
            float acc = 0.f;
            for (int p = lane; p < 320; p += 32) acc += tq[p] * cr[p];
            #pragma unroll
            for (int o = 16; o > 0; o >>= 1) acc += __shfl_down_sync(0xffffffffu, acc, o);
            if (lane == 0) sSc[t] = (acc + sT[640 + side]) * 0.05590169943749474f;
        }
    }
    __syncthreads();
    if (tid < 32) {   // softmax over 32 tokens
        float x = sSc[tid];
        float mx = x;
        #pragma unroll
        for (int o = 16; o > 0; o >>= 1) mx = fmaxf(mx, __shfl_xor_sync(0xffffffffu, mx, o));
        float e = expf(x - mx);
        float s = e;
        #pragma unroll
        for (int o = 16; o > 0; o >>= 1) s += __shfl_xor_sync(0xffffffffu, s, o);
        float ein = (tid < 16) ? e : 0.f;
        #pragma unroll
        for (int o = 16; o > 0; o >>= 1) ein += __shfl_xor_sync(0xffffffffu, ein, o);
        sPr[tid] = e / s;
        if (tid == 0) { sAl[0] = ein / s; sAl[1] = (s - ein) / s; }
    }
    __syncthreads();
    for (int col = tid; col < 640; col += 256) {   // weighted context sums
        int side = col >= 320;
        int p = col - side * 320;
        const float* a = sPr + side * 16;
        const float* c = sC + side * 16 * 320 + p;
        float acc = 0.f;
        #pragma unroll
        for (int t = 0; t < 16; t++) acc += a[t] * c[t * 320];
        sS[col] = acc;
    }
    if (tid == 0) { sS[640] = sAl[0]; sS[641] = sAl[1]; }
    __syncthreads();
    {   // 30 logits, 8 lanes each
        int k = tid >> 3, sub = tid & 7;
        float acc = 0.f;
        if (k < 30)
            for (int p = sub; p < 642; p += 8) acc += sS[p] * g_G[p * 30 + k];
        acc += __shfl_down_sync(0xffffffffu, acc, 4, 8);
        acc += __shfl_down_sync(0xffffffffu, acc, 2, 8);
        acc += __shfl_down_sync(0xffffffffu, acc, 1, 8);
        if (k < 30 && sub == 0) {
            float x = acc + g_r[k];
            out[(size_t)n * 30 + k] = x > 0.f ? x : expm1f(x);
        }
    }
}

extern "C" void kernel_launch(void* const* d_in, const int* in_sizes, int n_in,
                              void* d_out, int out_size)
{
    const float* X         = (const float*)d_in[0];
    const int*   in_idx    = (const int*)d_in[1];
    const int*   out_idx   = (const int*)d_in[2];
    const float* in_Wq     = (const float*)d_in[3];
    const float* in_Wk     = (const float*)d_in[4];
    const float* in_Wv     = (const float*)d_in[5];
    const float* in_qkv_w  = (const float*)d_in[6];
    const float* in_qkv_b  = (const float*)d_in[7];
    const float* in_o_w    = (const float*)d_in[8];
    const float* in_o_b    = (const float*)d_in[9];
    const float* out_Wq    = (const float*)d_in[10];
    const float* out_Wk    = (const float*)d_in[11];
    const float* out_Wv    = (const float*)d_in[12];
    const float* out_qkv_w = (const float*)d_in[13];
    const float* out_qkv_b = (const float*)d_in[14];
    const float* out_o_w   = (const float*)d_in[15];
    const float* out_o_b   = (const float*)d_in[16];
    const float* fin_qkv_w = (const float*)d_in[17];
    const float* fin_qkv_b = (const float*)d_in[18];
    const float* fin_o_w   = (const float*)d_in[19];
    const float* fin_o_b   = (const float*)d_in[20];
    const float* Wm        = (const float*)d_in[21];
    float* out = (float*)d_out;

    // Launch order: 4th app launch = k5_attn (ncu capture slot).
    // Deps: k4 needs k1+k3a; k5 needs k4; k2/k3b only needed before k6/k7.
    k1_prep<<<dim3(10, 10, 12), 256>>>(in_Wq, in_Wk, in_Wv, in_qkv_w,
                                       out_Wq, out_Wk, out_Wv, out_qkv_w,
                                       in_o_w, out_o_w, fin_qkv_w, fin_o_w, Wm);
    k3a_vec<<<6, 256>>>(fin_qkv_w, fin_qkv_b, in_o_b, out_o_b,
                        in_qkv_b, out_qkv_b, fin_o_b, Wm);
    k4_proj<<<dim3(30, 79), 256>>>(X);
    k5_attn<<<NN, 256>>>(in_idx, out_idx);
    k2_prep<<<dim3(10, 10, 4), 256>>>();
    k3b_vec<<<7, 320>>>();
    k6_tq<<<dim3(11, 79), 256>>>();
    k7_final<<<NN, 256>>>(out);
}

// round 16
// speedup vs baseline: 1.6539x; 1.0616x over previous
#include <cuda_runtime.h>
#include <math.h>
#include <stdint.h>

#define NN 10000
#define EE 320
#define YW 1920
#define TW 642
#define TWP 644   // padded leading dim for 642-wide buffers (float4 alignment)

// ---------------- device scratch ----------------
__device__ __align__(16) float g_Acat[EE * YW];
__device__ __align__(16) float g_bcat[YW];
__device__ __align__(16) float g_Nq[EE * EE];
__device__ __align__(16) float g_NkIn[EE * EE];
__device__ __align__(16) float g_NkOut[EE * EE];
__device__ __align__(16) float g_NvIn[EE * EE];
__device__ __align__(16) float g_NvOut[EE * EE];
__device__ __align__(16) float g_P[EE * 30];
__device__ __align__(16) float g_MT[EE * TWP];    // [320 x 644(pad)]: M_in | M_out | w_in | w_out
__device__ __align__(16) float g_vc[TW];          // v_in | v_out | const_in | const_out
__device__ __align__(16) float g_G[TW * 30];      // rows: Gin(320) | Gout(320) | gin | gout
__device__ __align__(16) float g_r[30];
__device__ __align__(16) float g_cq[EE];
__device__ __align__(16) float g_ckin[EE];
__device__ __align__(16) float g_ckout[EE];
__device__ __align__(16) float g_cvin[EE];
__device__ __align__(16) float g_cvout[EE];
__device__ __align__(16) float g_Y[(size_t)NN * YW];          // 76.8 MB
__device__ __align__(16) float g_C[(size_t)NN * 32 * EE];     // 409.6 MB
__device__ __align__(16) float g_TQE[(size_t)NN * TWP];       // 25.8 MB

// ---------------- generic 32x32 prep GEMM ----------------
__device__ void gemm32(const float* __restrict__ A, int lda, int tA,
                       const float* __restrict__ B, int ldb, int tB,
                       float* __restrict__ C, int ldc, int M, int Nc)
{
    __shared__ float As[32][33];
    __shared__ float Bs[32][33];
    int bi = blockIdx.x * 32, bj = blockIdx.y * 32;
    if (bi >= M || bj >= Nc) return;
    int tid = threadIdx.x, tx = tid & 15, ty = tid >> 4;
    float a00 = 0.f, a01 = 0.f, a10 = 0.f, a11 = 0.f;
    for (int kt = 0; kt < 320; kt += 32) {
        #pragma unroll
        for (int s = 0; s < 4; s++) {
            int li = tid + s * 256;
            int k = li & 31, r = li >> 5;
            int m = bi + r;
            As[k][r] = (m < M) ? (tA ? A[(size_t)(kt + k) * lda + m]
                                     : A[(size_t)m * lda + kt + k]) : 0.f;
            int nn = bj + r;
            Bs[k][r] = (nn < Nc) ? (tB ? B[(size_t)nn * ldb + kt + k]
                                       : B[(size_t)(kt + k) * ldb + nn]) : 0.f;
        }
        __syncthreads();
        #pragma unroll
        for (int k = 0; k < 32; k++) {
            float x0 = As[k][ty * 2], x1 = As[k][ty * 2 + 1];
            float y0 = Bs[k][tx * 2], y1 = Bs[k][tx * 2 + 1];
            a00 += x0 * y0; a01 += x0 * y1; a10 += x1 * y0; a11 += x1 * y1;
        }
        __syncthreads();
    }
    int r0 = bi + ty * 2, c0 = bj + tx * 2;
    if (r0 < M && c0 < Nc)         C[(size_t)r0 * ldc + c0]           = a00;
    if (r0 < M && c0 + 1 < Nc)     C[(size_t)r0 * ldc + c0 + 1]       = a01;
    if (r0 + 1 < M && c0 < Nc)     C[(size_t)(r0 + 1) * ldc + c0]     = a10;
    if (r0 + 1 < M && c0 + 1 < Nc) C[(size_t)(r0 + 1) * ldc + c0 + 1] = a11;
}

__global__ void __launch_bounds__(256) k1_prep(
    const float* in_Wq, const float* in_Wk, const float* in_Wv, const float* in_qkv_w,
    const float* out_Wq, const float* out_Wk, const float* out_Wv, const float* out_qkv_w,
    const float* in_o_w, const float* out_o_w, const float* fin_qkv_w,
    const float* fin_o_w, const float* Wm)
{
    switch (blockIdx.z) {
    case 0:  gemm32(in_Wq, 320, 0, in_qkv_w,           320, 1, g_Acat + 0,    1920, 320, 320); break;
    case 1:  gemm32(in_Wk, 320, 0, in_qkv_w + 102400,  320, 1, g_Acat + 320,  1920, 320, 320); break;
    case 2:  gemm32(in_Wv, 320, 0, in_qkv_w + 204800,  320, 1, g_Acat + 640,  1920, 320, 320); break;
    case 3:  gemm32(out_Wq, 320, 0, out_qkv_w,          320, 1, g_Acat + 960,  1920, 320, 320); break;
    case 4:  gemm32(out_Wk, 320, 0, out_qkv_w + 102400, 320, 1, g_Acat + 1280, 1920, 320, 320); break;
    case 5:  gemm32(out_Wv, 320, 0, out_qkv_w + 204800, 320, 1, g_Acat + 1600, 1920, 320, 320); break;
    case 6:  gemm32(fin_qkv_w,          320, 0, in_o_w,  320, 0, g_Nq,    320, 320, 320); break;
    case 7:  gemm32(fin_qkv_w + 102400, 320, 0, in_o_w,  320, 0, g_NkIn,  320, 320, 320); break;
    case 8:  gemm32(fin_qkv_w + 102400, 320, 0, out_o_w, 320, 0, g_NkOut, 320, 320, 320); break;
    case 9:  gemm32(fin_qkv_w + 204800, 320, 0, in_o_w,  320, 0, g_NvIn,  320, 320, 320); break;
    case 10: gemm32(fin_qkv_w + 204800, 320, 0, out_o_w, 320, 0, g_NvOut, 320, 320, 320); break;
    case 11: gemm32(fin_o_w, 320, 1, Wm, 30, 0, g_P, 30, 320, 30); break;
    }
}

__global__ void __launch_bounds__(256) k2_prep()
{
    switch (blockIdx.z) {
    case 0: gemm32(g_Nq,    320, 1, g_NkIn,  320, 0, g_MT,        TWP, 320, 320); break;
    case 1: gemm32(g_Nq,    320, 1, g_NkOut, 320, 0, g_MT + 320,  TWP, 320, 320); break;
    case 2: gemm32(g_NvIn,  320, 1, g_P,     30,  0, g_G,         30,  320, 30);  break;
    case 3: gemm32(g_NvOut, 320, 1, g_P,     30,  0, g_G + 9600,  30,  320, 30);  break;
    }
}

// ---------------- prep vectors level A ----------------
__global__ void __launch_bounds__(256) k3a_vec(
    const float* fqw, const float* fqb, const float* in_o_b, const float* out_o_b,
    const float* in_qkv_b, const float* out_qkv_b, const float* fin_o_b, const float* Wm)
{
    int z = blockIdx.x, tid = threadIdx.x;
    if (z == 5) {
        for (int t = tid; t < 1920; t += 256) {
            int cb = t / 320, m = t % 320;
            g_bcat[t] = (cb < 3 ? in_qkv_b : out_qkv_b)[(cb % 3) * 320 + m];
        }
        if (tid < 30) {
            float acc = 0.f;
            for (int j = 0; j < 320; j++) acc += fin_o_b[j] * Wm[j * 30 + tid];
            g_r[tid] = acc;
        }
        return;
    }
    __shared__ float sv[320];
    const float* A; const float* v; const float* b; float* out;
    switch (z) {
    case 0: A = fqw;           v = in_o_b;  b = fqb;       out = g_cq;    break;
    case 1: A = fqw + 102400;  v = in_o_b;  b = fqb + 320; out = g_ckin;  break;
    case 2: A = fqw + 102400;  v = out_o_b; b = fqb + 320; out = g_ckout; break;
    case 3: A = fqw + 204800;  v = in_o_b;  b = fqb + 640; out = g_cvin;  break;
    default:A = fqw + 204800;  v = out_o_b; b = fqb + 640; out = g_cvout; break;
    }
    for (int t = tid; t < 320; t += 256) sv[t] = v[t];
    __syncthreads();
    int w = tid >> 5, lane = tid & 31;
    for (int i = w; i < 320; i += 8) {
        float acc = 0.f;
        for (int j = lane; j < 320; j += 32) acc += A[(size_t)i * 320 + j] * sv[j];
        #pragma unroll
        for (int o = 16; o > 0; o >>= 1) acc += __shfl_down_sync(0xffffffffu, acc, o);
        if (lane == 0) out[i] = acc + b[i];
    }
}

// ---------------- prep vectors level B ----------------
__global__ void __launch_bounds__(320) k3b_vec()
{
    int z = blockIdx.x, tid = threadIdx.x;
    if (z == 6) {
        if (tid < 64) {
            int lane = tid & 31;
            const float* ck = (tid < 32) ? g_ckin : g_ckout;
            float acc = 0.f;
            for (int i = lane; i < 320; i += 32) acc += g_cq[i] * ck[i];
            #pragma unroll
            for (int o = 16; o > 0; o >>= 1) acc += __shfl_down_sync(0xffffffffu, acc, o);
            if (lane == 0) g_vc[640 + (tid >= 32)] = acc;
        }
        return;
    }
    __shared__ float sv[320];
    if (z >= 4) {  // gin / gout rows of G
        const float* cv = (z == 4) ? g_cvin : g_cvout;
        for (int t = tid; t < 320; t += 320) sv[t] = cv[t];
        __syncthreads();
        if (tid < 30) {
            float acc = 0.f;
            for (int i = 0; i < 320; i++) acc += sv[i] * g_P[i * 30 + tid];
            g_G[(z == 4 ? 640 : 641) * 30 + tid] = acc;
        }
        return;
    }
    const float* M; const float* v;
    switch (z) {
    case 0: M = g_NkIn;  v = g_cq;    break;
    case 1: M = g_NkOut; v = g_cq;    break;
    case 2: M = g_Nq;    v = g_ckin;  break;
    default:M = g_Nq;    v = g_ckout; break;
    }
    for (int t = tid; t < 320; t += 320) sv[t] = v[t];
    __syncthreads();
    if (tid < 320) {
        float acc = 0.f;
        for (int i = 0; i < 320; i++) acc += M[(size_t)i * 320 + tid] * sv[i];
        switch (z) {
        case 0: g_vc[tid] = acc; break;
        case 1: g_vc[320 + tid] = acc; break;
        case 2: g_MT[(size_t)tid * TWP + 640] = acc; break;
        default:g_MT[(size_t)tid * TWP + 641] = acc; break;
        }
    }
}

// ---- 128x64-tile double-buffered SGEMM, 8x4 micro: C = A@B + bias ----
__device__ __forceinline__ void gemm128x64(const float* __restrict__ A, int lda,
                                           const float* __restrict__ B, int ldb,
                                           const float* __restrict__ bias,
                                           float* __restrict__ C, int ldc, int M, int Nc)
{
    __shared__ __align__(16) float As[2][16 * 132];   // [k][row], 128 rows + pad
    __shared__ __align__(16) float Bs[2][16 * 68];    // [k][col], 64 cols + pad
    const int bi = blockIdx.y * 128, bj = blockIdx.x * 64;
    const int tid = threadIdx.x;
    const int tx = tid & 15, ty = tid >> 4;
    const int ar = tid >> 2, akc = tid & 3;
    const int brow = tid >> 4, bc4 = tid & 15;
    const int gr0 = bi + ar, gr1 = bi + ar + 64;
    const bool av0 = gr0 < M, av1 = gr1 < M;
    const int gc = bj + bc4 * 4;
    float acc[8][4] = {};
    float4 sa0, sa1, sb;

    auto load_g = [&](int kt) {
        sa0 = make_float4(0.f, 0.f, 0.f, 0.f);
        sa1 = sa0;
        if (av0) sa0 = *(const float4*)(A + (size_t)gr0 * lda + kt + akc * 4);
        if (av1) sa1 = *(const float4*)(A + (size_t)gr1 * lda + kt + akc * 4);
        const float* bp = B + (size_t)(kt + brow) * ldb + gc;
        if (gc + 3 < Nc) sb = *(const float4*)bp;
        else {
            sb.x = (gc + 0 < Nc) ? bp[0] : 0.f;
            sb.y = (gc + 1 < Nc) ? bp[1] : 0.f;
            sb.z = (gc + 2 < Nc) ? bp[2] : 0.f;
            sb.w = (gc + 3 < Nc) ? bp[3] : 0.f;
        }
    };
    auto store_s = [&](int buf) {
        float* as = As[buf];
        as[(akc * 4 + 0) * 132 + ar] = sa0.x;
        as[(akc * 4 + 1) * 132 + ar] = sa0.y;
        as[(akc * 4 + 2) * 132 + ar] = sa0.z;
        as[(akc * 4 + 3) * 132 + ar] = sa0.w;
        as[(akc * 4 + 0) * 132 + ar + 64] = sa1.x;
        as[(akc * 4 + 1) * 132 + ar + 64] = sa1.y;
        as[(akc * 4 + 2) * 132 + ar + 64] = sa1.z;
        as[(akc * 4 + 3) * 132 + ar + 64] = sa1.w;
        *(float4*)&Bs[buf][brow * 68 + bc4 * 4] = sb;
    };

    load_g(0);
    store_s(0);
    __syncthreads();

    const int nt = 320 / 16;
    for (int t = 0; t < nt; t++) {
        const int cur = t & 1;
        if (t + 1 < nt) load_g((t + 1) * 16);
        #pragma unroll
        for (int k = 0; k < 16; k++) {
            float af[8], bf[4];
            *(float4*)(af)     = *(const float4*)&As[cur][k * 132 + ty * 8];
            *(float4*)(af + 4) = *(const float4*)&As[cur][k * 132 + ty * 8 + 4];
            *(float4*)(bf)     = *(const float4*)&Bs[cur][k * 68 + tx * 4];
            #pragma unroll
            for (int i = 0; i < 8; i++)
                #pragma unroll
                for (int j = 0; j < 4; j++)
                    acc[i][j] += af[i] * bf[j];
        }
        if (t + 1 < nt) {
            store_s(1 - cur);
            __syncthreads();
        }
    }

    #pragma unroll
    for (int i = 0; i < 8; i++) {
        int r = bi + ty * 8 + i;
        if (r >= M) continue;
        int c0 = bj + tx * 4;
        if (c0 + 3 < Nc) {
            float4 o;
            o.x = acc[i][0] + bias[c0];
            o.y = acc[i][1] + bias[c0 + 1];
            o.z = acc[i][2] + bias[c0 + 2];
            o.w = acc[i][3] + bias[c0 + 3];
            *(float4*)(C + (size_t)r * ldc + c0) = o;
        } else {
            #pragma unroll
            for (int j = 0; j < 4; j++) {
                int c = c0 + j;
                if (c < Nc) C[(size_t)r * ldc + c] = acc[i][j] + bias[c];
            }
        }
    }
}

__global__ void __launch_bounds__(256) k4_proj(const float* __restrict__ X)
{
    gemm128x64(X, 320, g_Acat, 1920, g_bcat, g_Y, 1920, NN, 1920);
}

__global__ void __launch_bounds__(256) k6_tq()
{
    gemm128x64(g_C, 10240, g_MT, TWP, g_vc, g_TQE, TWP, NN, TW);
}

// ---------------- per-node 5-head attention; grid=(NN, 2) one side per block ----
__global__ void __launch_bounds__(256, 4) k5_attn(const int* __restrict__ in_idx,
                                                  const int* __restrict__ out_idx)
{
    __shared__ __align__(16) float sA[16 * 324];   // Q, then V
    __shared__ __align__(16) float sB[16 * 324];   // K
    __shared__ float sP[5 * 16 * 16];
    __shared__ int   sIdx[16];
    const int tid = threadIdx.x;
    const int n = blockIdx.x;
    const int side = blockIdx.y;
    const float4* Y4 = (const float4*)g_Y;

    if (tid < 16) {
        const int* idx = side ? out_idx : in_idx;
        sIdx[tid] = (tid == 0) ? n : idx[n * 15 + tid - 1];
    }
    __syncthreads();
    {   // gather Q->sA, K->sB
        float4* dA = (float4*)sA;
        float4* dB = (float4*)sB;
        int base = side * 240;
        #pragma unroll
        for (int k = 0; k < 5; k++) {
            int li = tid + k * 256;
            int row = li / 80, f4 = li % 80;
            size_t src = (size_t)sIdx[row] * 480 + base + f4;
            dA[row * 81 + f4] = Y4[src];
            dB[row * 81 + f4] = Y4[src + 80];
        }
    }
    __syncthreads();
    {   // scores: 2x2 micro over (l,m), heads split across thread groups
        const float4* Q4 = (const float4*)sA;
        const float4* K4 = (const float4*)sB;
        int l0 = ((tid >> 3) & 7) * 2;
        int m0 = (tid & 7) * 2;
        int h4 = tid >> 6;
        for (int h = h4; h < 5; h += 4) {
            float a00 = 0.f, a01 = 0.f, a10 = 0.f, a11 = 0.f;
            const float4* q0 = Q4 + l0 * 81 + h * 16;
            const float4* q1 = q0 + 81;
            const float4* k0 = K4 + m0 * 81 + h * 16;
            const float4* k1 = k0 + 81;
            #pragma unroll
            for (int i = 0; i < 16; i++) {
                float4 qa = q0[i], qb = q1[i], ka = k0[i], kb = k1[i];
                a00 += qa.x * ka.x + qa.y * ka.y + qa.z * ka.z + qa.w * ka.w;
                a01 += qa.x * kb.x + qa.y * kb.y + qa.z * kb.z + qa.w * kb.w;
                a10 += qb.x * ka.x + qb.y * ka.y + qb.z * ka.z + qb.w * ka.w;
                a11 += qb.x * kb.x + qb.y * kb.y + qb.z * kb.z + qb.w * kb.w;
            }
            int b = h * 256 + l0 * 16 + m0;
            sP[b]      = a00 * 0.125f;
            sP[b + 1]  = a01 * 0.125f;
            sP[b + 16] = a10 * 0.125f;
            sP[b + 17] = a11 * 0.125f;
        }
    }
    __syncthreads();
    {   // gather V->sA (Q dead)
        float4* dA = (float4*)sA;
        int base = side * 240 + 160;
        #pragma unroll
        for (int k = 0; k < 5; k++) {
            int li = tid + k * 256;
            int row = li / 80, f4 = li % 80;
            dA[row * 81 + f4] = Y4[(size_t)sIdx[row] * 480 + base + f4];
        }
    }
    if (tid < 80) {   // softmax per (h,l)
        float* row = sP + (tid >> 4) * 256 + (tid & 15) * 16;
        float mx = row[0];
        #pragma unroll
        for (int m = 1; m < 16; m++) mx = fmaxf(mx, row[m]);
        float e[16]; float s = 0.f;
        #pragma unroll
        for (int m = 0; m < 16; m++) { e[m] = expf(row[m] - mx); s += e[m]; }
        float inv = 1.f / s;
        #pragma unroll
        for (int m = 0; m < 16; m++) row[m] = e[m] * inv;
    }
    __syncthreads();
    {   // AV -> g_C
        const float4* V4 = (const float4*)sA;
        int l = tid >> 4, c = tid & 15;
        float4* Cout = (float4*)(g_C + ((size_t)n * 32 + side * 16 + l) * 320);
        #pragma unroll
        for (int j = 0; j < 5; j++) {
            float4 acc = make_float4(0.f, 0.f, 0.f, 0.f);
            const float* pr = sP + j * 256 + l * 16;
            const float4* vb = V4 + j * 16 + c;
            #pragma unroll
            for (int m = 0; m < 16; m++) {
                float w = pr[m];
                float4 v = vb[m * 81];
                acc.x += w * v.x; acc.y += w * v.y; acc.z += w * v.z; acc.w += w * v.w;
            }
            Cout[c + 16 * j] = acc;
        }
    }
}

// ---------------- per-node final attention + output projection + ELU ----------------
__global__ void __launch_bounds__(256) k7_final(float* __restrict__ out)
{
    __shared__ __align__(16) float sC[32 * 320];
    __shared__ float sT[644];
    __shared__ float sSc[32];
    __shared__ float sPr[32];
    __shared__ float sAl[2];
    __shared__ float sS[642];
    const int tid = threadIdx.x;
    const int n = blockIdx.x;
    {
        const float4* src = (const float4*)(g_C + (size_t)n * 10240);
        float4* dst = (float4*)sC;
        for (int k = tid; k < 2560; k += 256) dst[k] = src[k];
        const float* tq = g_TQE + (size_t)n * TWP;
        for (int k = tid; k < TW; k += 256) sT[k] = tq[k];
    }
    __syncthreads();
    {   // 32 scores: one warp per 4 tokens
        int w = tid >> 5, lane = tid & 31;
        #pragma unroll
        for (int q = 0; q < 4; q++) {
            int t = w * 4 + q;
            int side = t >> 4;
            const float* tq = sT + side * 320;
            const float* cr = sC + t * 320;
            float acc = 0.f;
            for (int p = lane; p < 320; p += 32) acc += tq[p] * cr[p];
            #pragma unroll
            for (int o = 16; o > 0; o >>= 1) acc += __shfl_down_sync(0xffffffffu, acc, o);
            if (lane == 0) sSc[t] = (acc + sT[640 + side]) * 0.05590169943749474f;
        }
    }
    __syncthreads();
    if (tid < 32) {   // softmax over 32 tokens
        float x = sSc[tid];
        float mx = x;
        #pragma unroll
        for (int o = 16; o > 0; o >>= 1) mx = fmaxf(mx, __shfl_xor_sync(0xffffffffu, mx, o));
        float e = expf(x - mx);
        float s = e;
        #pragma unroll
        for (int o = 16; o > 0; o >>= 1) s += __shfl_xor_sync(0xffffffffu, s, o);
        float ein = (tid < 16) ? e : 0.f;
        #pragma unroll
        for (int o = 16; o > 0; o >>= 1) ein += __shfl_xor_sync(0xffffffffu, ein, o);
        sPr[tid] = e / s;
        if (tid == 0) { sAl[0] = ein / s; sAl[1] = (s - ein) / s; }
    }
    __syncthreads();
    for (int col = tid; col < 640; col += 256) {   // weighted context sums
        int side = col >= 320;
        int p = col - side * 320;
        const float* a = sPr + side * 16;
        const float* c = sC + side * 16 * 320 + p;
        float acc = 0.f;
        #pragma unroll
        for (int t = 0; t < 16; t++) acc += a[t] * c[t * 320];
        sS[col] = acc;
    }
    if (tid == 0) { sS[640] = sAl[0]; sS[641] = sAl[1]; }
    __syncthreads();
    {   // 30 logits, 8 lanes each
        int k = tid >> 3, sub = tid & 7;
        float acc = 0.f;
        if (k < 30)
            for (int p = sub; p < 642; p += 8) acc += sS[p] * g_G[p * 30 + k];
        acc += __shfl_down_sync(0xffffffffu, acc, 4, 8);
        acc += __shfl_down_sync(0xffffffffu, acc, 2, 8);
        acc += __shfl_down_sync(0xffffffffu, acc, 1, 8);
        if (k < 30 && sub == 0) {
            float x = acc + g_r[k];
            out[(size_t)n * 30 + k] = x > 0.f ? x : expm1f(x);
        }
    }
}

extern "C" void kernel_launch(void* const* d_in, const int* in_sizes, int n_in,
                              void* d_out, int out_size)
{
    const float* X         = (const float*)d_in[0];
    const int*   in_idx    = (const int*)d_in[1];
    const int*   out_idx   = (const int*)d_in[2];
    const float* in_Wq     = (const float*)d_in[3];
    const float* in_Wk     = (const float*)d_in[4];
    const float* in_Wv     = (const float*)d_in[5];
    const float* in_qkv_w  = (const float*)d_in[6];
    const float* in_qkv_b  = (const float*)d_in[7];
    const float* in_o_w    = (const float*)d_in[8];
    const float* in_o_b    = (const float*)d_in[9];
    const float* out_Wq    = (const float*)d_in[10];
    const float* out_Wk    = (const float*)d_in[11];
    const float* out_Wv    = (const float*)d_in[12];
    const float* out_qkv_w = (const float*)d_in[13];
    const float* out_qkv_b = (const float*)d_in[14];
    const float* out_o_w   = (const float*)d_in[15];
    const float* out_o_b   = (const float*)d_in[16];
    const float* fin_qkv_w = (const float*)d_in[17];
    const float* fin_qkv_b = (const float*)d_in[18];
    const float* fin_o_w   = (const float*)d_in[19];
    const float* fin_o_b   = (const float*)d_in[20];
    const float* Wm        = (const float*)d_in[21];
    float* out = (float*)d_out;

    // Launch order: 4th app launch = k5_attn (ncu capture slot).
    k1_prep<<<dim3(10, 10, 12), 256>>>(in_Wq, in_Wk, in_Wv, in_qkv_w,
                                       out_Wq, out_Wk, out_Wv, out_qkv_w,
                                       in_o_w, out_o_w, fin_qkv_w, fin_o_w, Wm);
    k3a_vec<<<6, 256>>>(fin_qkv_w, fin_qkv_b, in_o_b, out_o_b,
                        in_qkv_b, out_qkv_b, fin_o_b, Wm);
    k4_proj<<<dim3(30, 79), 256>>>(X);
    k5_attn<<<dim3(NN, 2), 256>>>(in_idx, out_idx);
    k2_prep<<<dim3(10, 10, 4), 256>>>();
    k3b_vec<<<7, 320>>>();
    k6_tq<<<dim3(11, 79), 256>>>();
    k7_final<<<NN, 256>>>(out);
}